// round 9
// baseline (speedup 1.0000x reference)
#include <cuda_runtime.h>
#include <cuda_bf16.h>
#include <stdint.h>
#include <math.h>

#define Bv    8
#define Hdim  224
#define Wdim  224
#define Cch   192
#define NHh   6
#define HD    32
#define WSz   7
#define SSz   3
#define Nwin  49
#define NWH   32
#define NWW   32
#define NWIN  1024
#define Ltok  (Hdim*Wdim)
#define TOK   (Bv*Ltok)     // 401408
#define HID   768
#define CQKV  576

typedef __nv_bfloat16 bf16;

// ---------------- scratch (device globals) ------------------------------------
__device__ bf16 g_xw[(size_t)TOK * Cch];
__device__ bf16 g_qkv[(size_t)TOK * CQKV];
__device__ bf16 g_att[(size_t)TOK * Cch];
__device__ bf16 g_hid[(size_t)TOK * HID];
__device__ bf16 g_wqkv[Cch * CQKV];
__device__ bf16 g_wproj[Cch * Cch];
__device__ bf16 g_wfc1[Cch * HID];
__device__ bf16 g_wfc2[HID * Cch];

#define NQKV  (Cch*CQKV)
#define NPROJ (Cch*Cch)
#define NFC1  (Cch*HID)
#define NFC2  (HID*Cch)
#define NCVT  (NQKV+NPROJ+NFC1+NFC2)

// ---------------- fused weight fp32 -> bf16 -----------------------------------
__global__ void cvt_all_kernel(const float* __restrict__ qkv_w,
                               const float* __restrict__ proj_w,
                               const float* __restrict__ fc1_w,
                               const float* __restrict__ fc2_w)
{
    int i = blockIdx.x * 256 + threadIdx.x;
    if (i >= NCVT) return;
    if (i < NQKV) {
        g_wqkv[i] = __float2bfloat16(qkv_w[i]);
    } else if (i < NQKV + NPROJ) {
        int j = i - NQKV;
        g_wproj[j] = __float2bfloat16(proj_w[j]);
    } else if (i < NQKV + NPROJ + NFC1) {
        int j = i - NQKV - NPROJ;
        g_wfc1[j] = __float2bfloat16(fc1_w[j]);
    } else {
        int j = i - NQKV - NPROJ - NFC1;
        g_wfc2[j] = __float2bfloat16(fc2_w[j]);
    }
}

// ---------------- LN1 + shift + window-partition -------------------------------
__global__ void __launch_bounds__(256) ln1_window_kernel(
    const float* __restrict__ x, const float* __restrict__ g,
    const float* __restrict__ b)
{
    int warp = (blockIdx.x * blockDim.x + threadIdx.x) >> 5;
    int lane = threadIdx.x & 31;
    if (warp >= TOK) return;
    int bidx = warp / Ltok;
    int l    = warp % Ltok;
    const float* xr = x + (size_t)warp * Cch;
    float v[6];
    float s = 0.f;
    float ss = 0.f;
#pragma unroll
    for (int i = 0; i < 6; i++) {
        v[i] = xr[lane + 32 * i];
        s  += v[i];
        ss += v[i] * v[i];
    }
#pragma unroll
    for (int o = 16; o; o >>= 1) {
        s  += __shfl_xor_sync(0xffffffffu, s,  o);
        ss += __shfl_xor_sync(0xffffffffu, ss, o);
    }
    float mean = s * (1.f / Cch);
    float rstd = rsqrtf(ss * (1.f / Cch) - mean * mean + 1e-5f);

    int h = l / Wdim;
    int w = l % Wdim;
    int hs = h - SSz; if (hs < 0) hs += Hdim;
    int ws = w - SSz; if (ws < 0) ws += Wdim;
    int wh = hs / WSz;
    int r  = hs % WSz;
    int ww = ws / WSz;
    int c  = ws % WSz;
    int row = (bidx * NWIN + wh * NWW + ww) * Nwin + r * WSz + c;
    bf16* dst = g_xw + (size_t)row * Cch;
#pragma unroll
    for (int i = 0; i < 6; i++) {
        int ch = lane + 32 * i;
        dst[ch] = __float2bfloat16((v[i] - mean) * rstd * g[ch] + b[ch]);
    }
}

// ---------------- LN2 -----------------------------------------------------------
__global__ void __launch_bounds__(256) ln2_kernel(
    const float* __restrict__ x, const float* __restrict__ g,
    const float* __restrict__ b)
{
    int warp = (blockIdx.x * blockDim.x + threadIdx.x) >> 5;
    int lane = threadIdx.x & 31;
    if (warp >= TOK) return;
    const float* xr = x + (size_t)warp * Cch;
    float v[6];
    float s = 0.f;
    float ss = 0.f;
#pragma unroll
    for (int i = 0; i < 6; i++) {
        v[i] = xr[lane + 32 * i];
        s  += v[i];
        ss += v[i] * v[i];
    }
#pragma unroll
    for (int o = 16; o; o >>= 1) {
        s  += __shfl_xor_sync(0xffffffffu, s,  o);
        ss += __shfl_xor_sync(0xffffffffu, ss, o);
    }
    float mean = s * (1.f / Cch);
    float rstd = rsqrtf(ss * (1.f / Cch) - mean * mean + 1e-5f);
    bf16* dst = g_xw + (size_t)warp * Cch;
#pragma unroll
    for (int i = 0; i < 6; i++) {
        int ch = lane + 32 * i;
        dst[ch] = __float2bfloat16((v[i] - mean) * rstd * g[ch] + b[ch]);
    }
}

// ---------------- mma / ldmatrix helpers -----------------------------------------
__device__ __forceinline__ void ldsm_x4(uint32_t& r0, uint32_t& r1, uint32_t& r2,
                                        uint32_t& r3, const void* p)
{
    uint32_t a = (uint32_t)__cvta_generic_to_shared(p);
    asm volatile("ldmatrix.sync.aligned.m8n8.x4.shared.b16 {%0,%1,%2,%3},[%4];"
                 : "=r"(r0), "=r"(r1), "=r"(r2), "=r"(r3) : "r"(a));
}
__device__ __forceinline__ void ldsm_x4_t(uint32_t& r0, uint32_t& r1, uint32_t& r2,
                                          uint32_t& r3, const void* p)
{
    uint32_t a = (uint32_t)__cvta_generic_to_shared(p);
    asm volatile("ldmatrix.sync.aligned.m8n8.x4.trans.shared.b16 {%0,%1,%2,%3},[%4];"
                 : "=r"(r0), "=r"(r1), "=r"(r2), "=r"(r3) : "r"(a));
}
__device__ __forceinline__ void mma_bf16(float* c, const uint32_t* a, const uint32_t* b)
{
    asm volatile(
        "mma.sync.aligned.m16n8k16.row.col.f32.bf16.bf16.f32 "
        "{%0,%1,%2,%3},{%4,%5,%6,%7},{%8,%9},{%0,%1,%2,%3};"
        : "+f"(c[0]), "+f"(c[1]), "+f"(c[2]), "+f"(c[3])
        : "r"(a[0]), "r"(a[1]), "r"(a[2]), "r"(a[3]), "r"(b[0]), "r"(b[1]));
}
__device__ __forceinline__ void cp16(void* smem, const void* gmem)
{
    uint32_t a = (uint32_t)__cvta_generic_to_shared(smem);
    asm volatile("cp.async.cg.shared.global [%0], [%1], 16;" :: "r"(a), "l"(gmem));
}
__device__ __forceinline__ void cp_commit()
{
    asm volatile("cp.async.commit_group;" ::: "memory");
}
__device__ __forceinline__ void cp_wait_all()
{
    asm volatile("cp.async.wait_group 0;" ::: "memory");
}

// ---------------- bf16 tensor-core GEMM (BM=128, BN=96, cp.async 2-stage) ---------
#define BM 128
#define BN 96
#define BK 32
#define ASTRIDE 40
#define BSTRIDE 104

// MODE 0: bf16 store (qkv)
// MODE 1: fp32 store, window-reverse + unshift + residual -> d_out
// MODE 2: exact GELU -> bf16 store (hidden)
// MODE 3: fp32 += (fc2 residual into d_out)
template <int MODE>
__device__ __forceinline__ void hgemm_body(
    const bf16* A, const bf16* Bw, const float* bias, void* Cout,
    int Kd, int Nd, const float* resid)
{
    __shared__ bf16 As[2][BM][ASTRIDE];
    __shared__ bf16 Bs[2][BK][BSTRIDE];

    int tid  = threadIdx.x;
    int warp = tid >> 5;
    int lane = tid & 31;
    int wm = warp >> 1;      // 0..3 : 32-row strip
    int wn = warp & 1;       // 0..1 : 48-col strip
    int row0 = blockIdx.y * BM;
    int col0 = blockIdx.x * BN;

    float acc[2][6][4];
#pragma unroll
    for (int i = 0; i < 2; i++)
#pragma unroll
        for (int j = 0; j < 6; j++)
#pragma unroll
            for (int k = 0; k < 4; k++) acc[i][j][k] = 0.f;

    // A: 512 chunks of 16B; 2 per thread
    int ra0 = tid >> 2;
    int ka0 = (tid & 3) * 8;
    int ra1 = ra0 + 64;
    // B: 32 rows x 96 cols = 384 chunks; thread t does chunk t, thread t<128 also t+256
    int rb0 = tid / 12;
    int kb0 = (tid % 12) * 8;
    int rb1 = (tid + 256) / 12;
    int kb1 = ((tid + 256) % 12) * 8;
    bool b2 = (tid < 128);

    const bf16* Ag0 = A + (size_t)(row0 + ra0) * Kd + ka0;
    const bf16* Ag1 = A + (size_t)(row0 + ra1) * Kd + ka0;
    const bf16* Bg0 = Bw + (size_t)rb0 * Nd + col0 + kb0;
    const bf16* Bg1 = Bw + (size_t)rb1 * Nd + col0 + kb1;

    cp16(&As[0][ra0][ka0], Ag0);
    cp16(&As[0][ra1][ka0], Ag1);
    cp16(&Bs[0][rb0][kb0], Bg0);
    if (b2) cp16(&Bs[0][rb1][kb1], Bg1);
    cp_commit();

    int buf = 0;
    for (int k0 = 0; k0 < Kd; k0 += BK) {
        cp_wait_all();
        __syncthreads();
        if (k0 + BK < Kd) {
            int nb = buf ^ 1;
            cp16(&As[nb][ra0][ka0], Ag0 + k0 + BK);
            cp16(&As[nb][ra1][ka0], Ag1 + k0 + BK);
            cp16(&Bs[nb][rb0][kb0], Bg0 + (size_t)(k0 + BK) * Nd);
            if (b2) cp16(&Bs[nb][rb1][kb1], Bg1 + (size_t)(k0 + BK) * Nd);
            cp_commit();
        }

#pragma unroll
        for (int ks = 0; ks < 2; ks++) {
            uint32_t af[2][4];
            uint32_t bfr[6][2];
#pragma unroll
            for (int mt = 0; mt < 2; mt++)
                ldsm_x4(af[mt][0], af[mt][1], af[mt][2], af[mt][3],
                        &As[buf][wm * 32 + mt * 16 + (lane & 15)][ks * 16 + (lane >> 4) * 8]);
#pragma unroll
            for (int bt = 0; bt < 3; bt++) {
                uint32_t r0, r1, r2, r3;
                ldsm_x4_t(r0, r1, r2, r3,
                          &Bs[buf][ks * 16 + (lane & 15)][wn * 48 + bt * 16 + (lane >> 4) * 8]);
                bfr[bt * 2][0] = r0;
                bfr[bt * 2][1] = r1;
                bfr[bt * 2 + 1][0] = r2;
                bfr[bt * 2 + 1][1] = r3;
            }
#pragma unroll
            for (int mt = 0; mt < 2; mt++)
#pragma unroll
                for (int nt = 0; nt < 6; nt++)
                    mma_bf16(acc[mt][nt], af[mt], bfr[nt]);
        }
        buf ^= 1;
    }

#pragma unroll
    for (int mt = 0; mt < 2; mt++) {
#pragma unroll
        for (int rh = 0; rh < 2; rh++) {
            int row = row0 + wm * 32 + mt * 16 + rh * 8 + (lane >> 2);
            size_t dstrow;
            if (MODE == 1) {
                int win = row / Nwin;
                int n = row % Nwin;
                int bb = win / NWIN;
                int w_ = win % NWIN;
                int wh = w_ / NWW;
                int ww = w_ % NWW;
                int h = wh * WSz + n / WSz + SSz; if (h >= Hdim) h -= Hdim;
                int w = ww * WSz + n % WSz + SSz; if (w >= Wdim) w -= Wdim;
                dstrow = ((size_t)bb * Ltok + h * Wdim + w) * Cch;
            } else {
                dstrow = (size_t)row * Nd;
            }
#pragma unroll
            for (int nt = 0; nt < 6; nt++) {
                int col = col0 + wn * 48 + nt * 8 + (lane & 3) * 2;
                float v0 = acc[mt][nt][rh * 2 + 0] + bias[col];
                float v1 = acc[mt][nt][rh * 2 + 1] + bias[col + 1];
                if (MODE == 0) {
                    *(__nv_bfloat162*)((bf16*)Cout + dstrow + col) =
                        __halves2bfloat162(__float2bfloat16(v0), __float2bfloat16(v1));
                } else if (MODE == 2) {
                    float g0 = 0.5f * v0 * (1.f + erff(v0 * 0.7071067811865475f));
                    float g1 = 0.5f * v1 * (1.f + erff(v1 * 0.7071067811865475f));
                    *(__nv_bfloat162*)((bf16*)Cout + dstrow + col) =
                        __halves2bfloat162(__float2bfloat16(g0), __float2bfloat16(g1));
                } else if (MODE == 1) {
                    float* o = (float*)Cout + dstrow + col;
                    o[0] = resid[dstrow + col]     + v0;
                    o[1] = resid[dstrow + col + 1] + v1;
                } else {
                    float* o = (float*)Cout + dstrow + col;
                    o[0] += v0;
                    o[1] += v1;
                }
            }
        }
    }
}

// ---------------- concrete GEMM wrappers ------------------------------------------
__global__ void __launch_bounds__(256) hgemm_qkv(const float* __restrict__ bias)
{
    hgemm_body<0>(g_xw, g_wqkv, bias, g_qkv, Cch, CQKV, (const float*)0);
}
__global__ void __launch_bounds__(256) hgemm_proj(const float* __restrict__ bias,
                                                  float* __restrict__ out,
                                                  const float* __restrict__ resid)
{
    hgemm_body<1>(g_att, g_wproj, bias, out, Cch, Cch, resid);
}
__global__ void __launch_bounds__(256) hgemm_fc1(const float* __restrict__ bias)
{
    hgemm_body<2>(g_xw, g_wfc1, bias, g_hid, Cch, HID, (const float*)0);
}
__global__ void __launch_bounds__(256) hgemm_fc2(const float* __restrict__ bias,
                                                 float* __restrict__ out)
{
    hgemm_body<3>(g_hid, g_wfc2, bias, out, HID, Cch, (const float*)0);
}

// ---------------- windowed attention: HMMA + register softmax ----------------------
__global__ void __launch_bounds__(128) attn_kernel(const float* __restrict__ rpb_table)
{
    __shared__ bf16  qs[64][40];
    __shared__ bf16  ks_[64][40];
    __shared__ bf16  vs[64][40];
    __shared__ bf16  ps[64][72];
    __shared__ float rpb[169];
    __shared__ int   grp[Nwin];

    int tid  = threadIdx.x;
    int warp = tid >> 5;
    int lane = tid & 31;

    int bh   = blockIdx.x;
    int head = bh % NHh;
    int win  = bh / NHh;
    int wwin = win % NWIN;
    int wh = wwin / NWW;
    int ww = wwin % NWW;

    const bf16* base = g_qkv + (size_t)win * Nwin * CQKV + head * HD;
    for (int idx = tid; idx < 196; idx += 128) {
        int row = idx >> 2;
        int c   = (idx & 3) * 8;
        const bf16* src = base + (size_t)row * CQKV + c;
        *(uint4*)&qs[row][c]  = *(const uint4*)(src);
        *(uint4*)&ks_[row][c] = *(const uint4*)(src + Cch);
        *(uint4*)&vs[row][c]  = *(const uint4*)(src + 2 * Cch);
    }
    for (int idx = tid; idx < 150; idx += 128) {
        int r  = 49 + idx / 10;
        int c4 = (idx % 10) * 4;
        uint2 z = make_uint2(0u, 0u);
        *(uint2*)&qs[r][c4]  = z;
        *(uint2*)&ks_[r][c4] = z;
        *(uint2*)&vs[r][c4]  = z;
    }
    for (int idx = tid; idx < 169; idx += 128)
        rpb[idx] = rpb_table[idx * NHh + head];
    if (tid < Nwin) {
        int r = tid / WSz;
        int c = tid % WSz;
        int hs  = wh * WSz + r;
        int wsc = ww * WSz + c;
        int gh = hs  < Hdim - WSz ? 0 : (hs  < Hdim - SSz ? 1 : 2);
        int gw = wsc < Wdim - WSz ? 0 : (wsc < Wdim - SSz ? 1 : 2);
        grp[tid] = gh * 3 + gw;
    }
    __syncthreads();

    int m0 = warp * 16;
    float c[8][4];
#pragma unroll
    for (int nt = 0; nt < 8; nt++)
#pragma unroll
        for (int e = 0; e < 4; e++) c[nt][e] = 0.f;
    {
        uint32_t a[2][4];
#pragma unroll
        for (int ksx = 0; ksx < 2; ksx++)
            ldsm_x4(a[ksx][0], a[ksx][1], a[ksx][2], a[ksx][3],
                    &qs[m0 + (lane & 15)][ksx * 16 + (lane >> 4) * 8]);
#pragma unroll
        for (int jt = 0; jt < 4; jt++) {
#pragma unroll
            for (int ksx = 0; ksx < 2; ksx++) {
                uint32_t r0, r1, r2, r3;
                ldsm_x4(r0, r1, r2, r3,
                        &ks_[jt * 16 + (lane & 15)][ksx * 16 + (lane >> 4) * 8]);
                uint32_t b0[2];
                uint32_t b1[2];
                b0[0] = r0; b0[1] = r2;
                b1[0] = r1; b1[1] = r3;
                mma_bf16(c[jt * 2],     a[ksx], b0);
                mma_bf16(c[jt * 2 + 1], a[ksx], b1);
            }
        }
    }

    {
        const float scale = 0.1767766952966369f;
        int i0 = m0 + (lane >> 2);
        int i1 = i0 + 8;
        int ri0 = i0 / WSz, ci0 = i0 % WSz;
        int ri1 = i1 / WSz, ci1 = i1 % WSz;
        int v0ok = (i0 < Nwin);
        int v1ok = (i1 < Nwin);
        int gi0 = v0ok ? grp[i0] : 0;
        int gi1 = v1ok ? grp[i1] : 0;

#pragma unroll
        for (int nt = 0; nt < 8; nt++) {
#pragma unroll
            for (int e = 0; e < 2; e++) {
                int j = nt * 8 + (lane & 3) * 2 + e;
                if (j < Nwin) {
                    int rj = j / WSz;
                    int cj = j % WSz;
                    int gj = grp[j];
                    float b0 = rpb[(ri0 - rj + 6) * 13 + (ci0 - cj + 6)];
                    float b1 = rpb[(ri1 - rj + 6) * 13 + (ci1 - cj + 6)];
                    float s0 = c[nt][e] * scale + b0 + (gi0 != gj ? -100.f : 0.f);
                    float s1 = c[nt][2 + e] * scale + b1 + (gi1 != gj ? -100.f : 0.f);
                    c[nt][e]     = v0ok ? s0 : -1e30f;
                    c[nt][2 + e] = v1ok ? s1 : -1e30f;
                } else {
                    c[nt][e]     = -1e30f;
                    c[nt][2 + e] = -1e30f;
                }
            }
        }

        float mx0 = -1e30f;
        float mx1 = -1e30f;
#pragma unroll
        for (int nt = 0; nt < 8; nt++) {
            mx0 = fmaxf(mx0, fmaxf(c[nt][0], c[nt][1]));
            mx1 = fmaxf(mx1, fmaxf(c[nt][2], c[nt][3]));
        }
        mx0 = fmaxf(mx0, __shfl_xor_sync(0xffffffffu, mx0, 1));
        mx0 = fmaxf(mx0, __shfl_xor_sync(0xffffffffu, mx0, 2));
        mx1 = fmaxf(mx1, __shfl_xor_sync(0xffffffffu, mx1, 1));
        mx1 = fmaxf(mx1, __shfl_xor_sync(0xffffffffu, mx1, 2));

        float sm0 = 0.f;
        float sm1 = 0.f;
#pragma unroll
        for (int nt = 0; nt < 8; nt++) {
            c[nt][0] = __expf(c[nt][0] - mx0);
            c[nt][1] = __expf(c[nt][1] - mx0);
            c[nt][2] = __expf(c[nt][2] - mx1);
            c[nt][3] = __expf(c[nt][3] - mx1);
            sm0 += c[nt][0] + c[nt][1];
            sm1 += c[nt][2] + c[nt][3];
        }
        sm0 += __shfl_xor_sync(0xffffffffu, sm0, 1);
        sm0 += __shfl_xor_sync(0xffffffffu, sm0, 2);
        sm1 += __shfl_xor_sync(0xffffffffu, sm1, 1);
        sm1 += __shfl_xor_sync(0xffffffffu, sm1, 2);
        float inv0 = 1.f / sm0;
        float inv1 = 1.f / sm1;

        int j0 = (lane & 3) * 2;
#pragma unroll
        for (int nt = 0; nt < 8; nt++) {
            *(__nv_bfloat162*)&ps[i0][nt * 8 + j0] =
                __halves2bfloat162(__float2bfloat16(c[nt][0] * inv0),
                                   __float2bfloat16(c[nt][1] * inv0));
            *(__nv_bfloat162*)&ps[i1][nt * 8 + j0] =
                __halves2bfloat162(__float2bfloat16(c[nt][2] * inv1),
                                   __float2bfloat16(c[nt][3] * inv1));
        }
    }
    __syncthreads();

    {
        float o[4][4];
#pragma unroll
        for (int nt = 0; nt < 4; nt++)
#pragma unroll
            for (int e = 0; e < 4; e++) o[nt][e] = 0.f;

#pragma unroll
        for (int ksx = 0; ksx < 4; ksx++) {
            uint32_t a[4];
            ldsm_x4(a[0], a[1], a[2], a[3],
                    &ps[m0 + (lane & 15)][ksx * 16 + (lane >> 4) * 8]);
#pragma unroll
            for (int bt = 0; bt < 2; bt++) {
                uint32_t r0, r1, r2, r3;
                ldsm_x4_t(r0, r1, r2, r3,
                          &vs[ksx * 16 + (lane & 15)][bt * 16 + (lane >> 4) * 8]);
                uint32_t b0[2];
                uint32_t b1[2];
                b0[0] = r0; b0[1] = r1;
                b1[0] = r2; b1[1] = r3;
                mma_bf16(o[bt * 2],     a, b0);
                mma_bf16(o[bt * 2 + 1], a, b1);
            }
        }

        bf16* outw = g_att + (size_t)win * Nwin * Cch + head * HD;
        int i0 = m0 + (lane >> 2);
#pragma unroll
        for (int nt = 0; nt < 4; nt++) {
            int d = nt * 8 + (lane & 3) * 2;
            if (i0 < Nwin) {
                *(__nv_bfloat162*)(outw + (size_t)i0 * Cch + d) =
                    __halves2bfloat162(__float2bfloat16(o[nt][0]), __float2bfloat16(o[nt][1]));
            }
            if (i0 + 8 < Nwin) {
                *(__nv_bfloat162*)(outw + (size_t)(i0 + 8) * Cch + d) =
                    __halves2bfloat162(__float2bfloat16(o[nt][2]), __float2bfloat16(o[nt][3]));
            }
        }
    }
}

// ---------------- launch ----------------------------------------------------------
extern "C" void kernel_launch(void* const* d_in, const int* in_sizes, int n_in,
                              void* d_out, int out_size)
{
    const float* x       = (const float*)d_in[0];
    const float* norm1_g = (const float*)d_in[1];
    const float* norm1_b = (const float*)d_in[2];
    const float* qkv_w   = (const float*)d_in[3];
    const float* qkv_b   = (const float*)d_in[4];
    const float* rpb_t   = (const float*)d_in[5];
    const float* proj_w  = (const float*)d_in[6];
    const float* proj_b  = (const float*)d_in[7];
    const float* norm2_g = (const float*)d_in[8];
    const float* norm2_b = (const float*)d_in[9];
    const float* fc1_w   = (const float*)d_in[10];
    const float* fc1_b   = (const float*)d_in[11];
    const float* fc2_w   = (const float*)d_in[12];
    const float* fc2_b   = (const float*)d_in[13];
    float* out = (float*)d_out;

    dim3 cvt_grid((NCVT + 255) / 256);
    cvt_all_kernel<<<cvt_grid, 256>>>(qkv_w, proj_w, fc1_w, fc2_w);

    dim3 ln_grid(TOK / 8);
    ln1_window_kernel<<<ln_grid, 256>>>(x, norm1_g, norm1_b);

    dim3 qkv_grid(CQKV / BN, TOK / BM);
    hgemm_qkv<<<qkv_grid, 256>>>(qkv_b);

    dim3 attn_grid((TOK / Nwin) * NHh);
    attn_kernel<<<attn_grid, 128>>>(rpb_t);

    dim3 proj_grid(Cch / BN, TOK / BM);
    hgemm_proj<<<proj_grid, 256>>>(proj_b, out, x);

    ln2_kernel<<<ln_grid, 256>>>(out, norm2_g, norm2_b);

    dim3 fc1_grid(HID / BN, TOK / BM);
    hgemm_fc1<<<fc1_grid, 256>>>(fc1_b);

    dim3 fc2_grid(Cch / BN, TOK / BM);
    hgemm_fc2<<<fc2_grid, 256>>>(fc2_b, out);
}

// round 10
// speedup vs baseline: 1.0800x; 1.0800x over previous
#include <cuda_runtime.h>
#include <cuda_bf16.h>
#include <stdint.h>
#include <math.h>

#define Bv    8
#define Hdim  224
#define Wdim  224
#define Cch   192
#define NHh   6
#define HD    32
#define WSz   7
#define SSz   3
#define Nwin  49
#define NWH   32
#define NWW   32
#define NWIN  1024
#define Ltok  (Hdim*Wdim)
#define TOK   (Bv*Ltok)     // 401408
#define HID   768
#define CQKV  576

typedef __nv_bfloat16 bf16;

// ---------------- scratch (device globals) ------------------------------------
__device__ bf16 g_xw[(size_t)TOK * Cch];
__device__ bf16 g_qkv[(size_t)TOK * CQKV];
__device__ bf16 g_att[(size_t)TOK * Cch];
__device__ bf16 g_hid[(size_t)TOK * HID];
__device__ bf16 g_wqkv[Cch * CQKV];
__device__ bf16 g_wproj[Cch * Cch];
__device__ bf16 g_wfc1[Cch * HID];
__device__ bf16 g_wfc2[HID * Cch];

#define NQKV  (Cch*CQKV)
#define NPROJ (Cch*Cch)
#define NFC1  (Cch*HID)
#define NFC2  (HID*Cch)
#define NCVT  (NQKV+NPROJ+NFC1+NFC2)

// ---------------- fused weight fp32 -> bf16 -----------------------------------
__global__ void cvt_all_kernel(const float* __restrict__ qkv_w,
                               const float* __restrict__ proj_w,
                               const float* __restrict__ fc1_w,
                               const float* __restrict__ fc2_w)
{
    int i = blockIdx.x * 256 + threadIdx.x;
    if (i >= NCVT) return;
    if (i < NQKV) {
        g_wqkv[i] = __float2bfloat16(qkv_w[i]);
    } else if (i < NQKV + NPROJ) {
        int j = i - NQKV;
        g_wproj[j] = __float2bfloat16(proj_w[j]);
    } else if (i < NQKV + NPROJ + NFC1) {
        int j = i - NQKV - NPROJ;
        g_wfc1[j] = __float2bfloat16(fc1_w[j]);
    } else {
        int j = i - NQKV - NPROJ - NFC1;
        g_wfc2[j] = __float2bfloat16(fc2_w[j]);
    }
}

// ---------------- LN1 + shift + window-partition -------------------------------
__global__ void __launch_bounds__(256) ln1_window_kernel(
    const float* __restrict__ x, const float* __restrict__ g,
    const float* __restrict__ b)
{
    int warp = (blockIdx.x * blockDim.x + threadIdx.x) >> 5;
    int lane = threadIdx.x & 31;
    if (warp >= TOK) return;
    int bidx = warp / Ltok;
    int l    = warp % Ltok;
    const float* xr = x + (size_t)warp * Cch;
    float v[6];
    float s = 0.f;
    float ss = 0.f;
#pragma unroll
    for (int i = 0; i < 6; i++) {
        v[i] = xr[lane + 32 * i];
        s  += v[i];
        ss += v[i] * v[i];
    }
#pragma unroll
    for (int o = 16; o; o >>= 1) {
        s  += __shfl_xor_sync(0xffffffffu, s,  o);
        ss += __shfl_xor_sync(0xffffffffu, ss, o);
    }
    float mean = s * (1.f / Cch);
    float rstd = rsqrtf(ss * (1.f / Cch) - mean * mean + 1e-5f);

    int h = l / Wdim;
    int w = l % Wdim;
    int hs = h - SSz; if (hs < 0) hs += Hdim;
    int ws = w - SSz; if (ws < 0) ws += Wdim;
    int wh = hs / WSz;
    int r  = hs % WSz;
    int ww = ws / WSz;
    int c  = ws % WSz;
    int row = (bidx * NWIN + wh * NWW + ww) * Nwin + r * WSz + c;
    bf16* dst = g_xw + (size_t)row * Cch;
#pragma unroll
    for (int i = 0; i < 6; i++) {
        int ch = lane + 32 * i;
        dst[ch] = __float2bfloat16((v[i] - mean) * rstd * g[ch] + b[ch]);
    }
}

// ---------------- LN2 -----------------------------------------------------------
__global__ void __launch_bounds__(256) ln2_kernel(
    const float* __restrict__ x, const float* __restrict__ g,
    const float* __restrict__ b)
{
    int warp = (blockIdx.x * blockDim.x + threadIdx.x) >> 5;
    int lane = threadIdx.x & 31;
    if (warp >= TOK) return;
    const float* xr = x + (size_t)warp * Cch;
    float v[6];
    float s = 0.f;
    float ss = 0.f;
#pragma unroll
    for (int i = 0; i < 6; i++) {
        v[i] = xr[lane + 32 * i];
        s  += v[i];
        ss += v[i] * v[i];
    }
#pragma unroll
    for (int o = 16; o; o >>= 1) {
        s  += __shfl_xor_sync(0xffffffffu, s,  o);
        ss += __shfl_xor_sync(0xffffffffu, ss, o);
    }
    float mean = s * (1.f / Cch);
    float rstd = rsqrtf(ss * (1.f / Cch) - mean * mean + 1e-5f);
    bf16* dst = g_xw + (size_t)warp * Cch;
#pragma unroll
    for (int i = 0; i < 6; i++) {
        int ch = lane + 32 * i;
        dst[ch] = __float2bfloat16((v[i] - mean) * rstd * g[ch] + b[ch]);
    }
}

// ---------------- mma / ldmatrix helpers -----------------------------------------
__device__ __forceinline__ void ldsm_x4(uint32_t& r0, uint32_t& r1, uint32_t& r2,
                                        uint32_t& r3, const void* p)
{
    uint32_t a = (uint32_t)__cvta_generic_to_shared(p);
    asm volatile("ldmatrix.sync.aligned.m8n8.x4.shared.b16 {%0,%1,%2,%3},[%4];"
                 : "=r"(r0), "=r"(r1), "=r"(r2), "=r"(r3) : "r"(a));
}
__device__ __forceinline__ void ldsm_x4_t(uint32_t& r0, uint32_t& r1, uint32_t& r2,
                                          uint32_t& r3, const void* p)
{
    uint32_t a = (uint32_t)__cvta_generic_to_shared(p);
    asm volatile("ldmatrix.sync.aligned.m8n8.x4.trans.shared.b16 {%0,%1,%2,%3},[%4];"
                 : "=r"(r0), "=r"(r1), "=r"(r2), "=r"(r3) : "r"(a));
}
__device__ __forceinline__ void mma_bf16(float* c, const uint32_t* a, const uint32_t* b)
{
    asm volatile(
        "mma.sync.aligned.m16n8k16.row.col.f32.bf16.bf16.f32 "
        "{%0,%1,%2,%3},{%4,%5,%6,%7},{%8,%9},{%0,%1,%2,%3};"
        : "+f"(c[0]), "+f"(c[1]), "+f"(c[2]), "+f"(c[3])
        : "r"(a[0]), "r"(a[1]), "r"(a[2]), "r"(a[3]), "r"(b[0]), "r"(b[1]));
}
__device__ __forceinline__ void cp16(void* smem, const void* gmem)
{
    uint32_t a = (uint32_t)__cvta_generic_to_shared(smem);
    asm volatile("cp.async.cg.shared.global [%0], [%1], 16;" :: "r"(a), "l"(gmem));
}
__device__ __forceinline__ void cp_commit()
{
    asm volatile("cp.async.commit_group;" ::: "memory");
}
__device__ __forceinline__ void cp_wait_all()
{
    asm volatile("cp.async.wait_group 0;" ::: "memory");
}

// ---------------- bf16 tensor-core GEMM (cp.async double-buffered, runtime K) -----
#define BM 128
#define BN 64
#define BK 32
#define ASTRIDE 40
#define BSTRIDE 72

// MODE 0: bf16 store (qkv)
// MODE 1: fp32 store, window-reverse + unshift + residual -> d_out
// MODE 2: exact GELU -> bf16 store (hidden)
// MODE 3: fp32 += (fc2 residual into d_out)
template <int MODE>
__device__ __forceinline__ void hgemm_body(
    const bf16* A, const bf16* Bw, const float* bias, void* Cout,
    int Kd, int Nd, const float* resid)
{
    __shared__ bf16 As[2][BM][ASTRIDE];
    __shared__ bf16 Bs[2][BK][BSTRIDE];

    int tid  = threadIdx.x;
    int warp = tid >> 5;
    int lane = tid & 31;
    int wm = warp >> 1;
    int wn = warp & 1;
    int row0 = blockIdx.y * BM;
    int col0 = blockIdx.x * BN;

    float acc[2][4][4];
#pragma unroll
    for (int i = 0; i < 2; i++)
#pragma unroll
        for (int j = 0; j < 4; j++)
#pragma unroll
            for (int k = 0; k < 4; k++) acc[i][j][k] = 0.f;

    int ra0 = tid >> 2;
    int ka0 = (tid & 3) * 8;
    int ra1 = ra0 + 64;
    int rb = tid >> 3;
    int kb = (tid & 7) * 8;

    const bf16* Ag0 = A + (size_t)(row0 + ra0) * Kd + ka0;
    const bf16* Ag1 = A + (size_t)(row0 + ra1) * Kd + ka0;
    const bf16* Bg  = Bw + (size_t)rb * Nd + col0 + kb;

    cp16(&As[0][ra0][ka0], Ag0);
    cp16(&As[0][ra1][ka0], Ag1);
    cp16(&Bs[0][rb][kb],   Bg);
    cp_commit();

    int buf = 0;
    for (int k0 = 0; k0 < Kd; k0 += BK) {
        cp_wait_all();
        __syncthreads();
        if (k0 + BK < Kd) {
            int nb = buf ^ 1;
            cp16(&As[nb][ra0][ka0], Ag0 + k0 + BK);
            cp16(&As[nb][ra1][ka0], Ag1 + k0 + BK);
            cp16(&Bs[nb][rb][kb],   Bg + (size_t)(k0 + BK) * Nd);
            cp_commit();
        }

#pragma unroll
        for (int ks = 0; ks < 2; ks++) {
            uint32_t af[2][4];
            uint32_t bfr[4][2];
#pragma unroll
            for (int mt = 0; mt < 2; mt++)
                ldsm_x4(af[mt][0], af[mt][1], af[mt][2], af[mt][3],
                        &As[buf][wm * 32 + mt * 16 + (lane & 15)][ks * 16 + (lane >> 4) * 8]);
#pragma unroll
            for (int bt = 0; bt < 2; bt++) {
                uint32_t r0, r1, r2, r3;
                ldsm_x4_t(r0, r1, r2, r3,
                          &Bs[buf][ks * 16 + (lane & 15)][wn * 32 + bt * 16 + (lane >> 4) * 8]);
                bfr[bt * 2][0] = r0;
                bfr[bt * 2][1] = r1;
                bfr[bt * 2 + 1][0] = r2;
                bfr[bt * 2 + 1][1] = r3;
            }
#pragma unroll
            for (int mt = 0; mt < 2; mt++)
#pragma unroll
                for (int nt = 0; nt < 4; nt++)
                    mma_bf16(acc[mt][nt], af[mt], bfr[nt]);
        }
        buf ^= 1;
    }

#pragma unroll
    for (int mt = 0; mt < 2; mt++) {
#pragma unroll
        for (int rh = 0; rh < 2; rh++) {
            int row = row0 + wm * 32 + mt * 16 + rh * 8 + (lane >> 2);
            size_t dstrow;
            if (MODE == 1) {
                int win = row / Nwin;
                int n = row % Nwin;
                int bb = win / NWIN;
                int w_ = win % NWIN;
                int wh = w_ / NWW;
                int ww = w_ % NWW;
                int h = wh * WSz + n / WSz + SSz; if (h >= Hdim) h -= Hdim;
                int w = ww * WSz + n % WSz + SSz; if (w >= Wdim) w -= Wdim;
                dstrow = ((size_t)bb * Ltok + h * Wdim + w) * Cch;
            } else {
                dstrow = (size_t)row * Nd;
            }
#pragma unroll
            for (int nt = 0; nt < 4; nt++) {
                int col = col0 + wn * 32 + nt * 8 + (lane & 3) * 2;
                float v0 = acc[mt][nt][rh * 2 + 0] + bias[col];
                float v1 = acc[mt][nt][rh * 2 + 1] + bias[col + 1];
                if (MODE == 0) {
                    *(__nv_bfloat162*)((bf16*)Cout + dstrow + col) =
                        __halves2bfloat162(__float2bfloat16(v0), __float2bfloat16(v1));
                } else if (MODE == 2) {
                    float g0 = 0.5f * v0 * (1.f + erff(v0 * 0.7071067811865475f));
                    float g1 = 0.5f * v1 * (1.f + erff(v1 * 0.7071067811865475f));
                    *(__nv_bfloat162*)((bf16*)Cout + dstrow + col) =
                        __halves2bfloat162(__float2bfloat16(g0), __float2bfloat16(g1));
                } else if (MODE == 1) {
                    float* o = (float*)Cout + dstrow + col;
                    o[0] = resid[dstrow + col]     + v0;
                    o[1] = resid[dstrow + col + 1] + v1;
                } else {
                    float* o = (float*)Cout + dstrow + col;
                    o[0] += v0;
                    o[1] += v1;
                }
            }
        }
    }
}

// ---------------- concrete GEMM wrappers ------------------------------------------
__global__ void __launch_bounds__(256) hgemm_qkv(const float* __restrict__ bias)
{
    hgemm_body<0>(g_xw, g_wqkv, bias, g_qkv, Cch, CQKV, (const float*)0);
}
__global__ void __launch_bounds__(256) hgemm_proj(const float* __restrict__ bias,
                                                  float* __restrict__ out,
                                                  const float* __restrict__ resid)
{
    hgemm_body<1>(g_att, g_wproj, bias, out, Cch, Cch, resid);
}
__global__ void __launch_bounds__(256) hgemm_fc1(const float* __restrict__ bias)
{
    hgemm_body<2>(g_xw, g_wfc1, bias, g_hid, Cch, HID, (const float*)0);
}
__global__ void __launch_bounds__(256) hgemm_fc2(const float* __restrict__ bias,
                                                 float* __restrict__ out)
{
    hgemm_body<3>(g_hid, g_wfc2, bias, out, HID, Cch, (const float*)0);
}

// ---------------- windowed attention: 2 heads per block, HMMA + reg softmax --------
// block = (window, head-pair); 256 threads; warps 0-3 -> head hh=0, warps 4-7 -> hh=1
// ps (64x72) aliases the q+k tiles (phase-1 only), guarded by __syncthreads.
__global__ void __launch_bounds__(256) attn_kernel(const float* __restrict__ rpb_table)
{
    __shared__ bf16  qk[2][2][64][40];   // [head][0=q,1=k][row][col]; ps aliases this
    __shared__ bf16  vs[2][64][40];
    __shared__ float rpb[2][169];
    __shared__ int   grp[Nwin];

    int tid  = threadIdx.x;
    int warp = tid >> 5;
    int lane = tid & 31;
    int hh   = warp >> 2;        // head within pair (compute phase)
    int wg   = warp & 3;         // warp within head group
    int m0   = wg * 16;

    int blk  = blockIdx.x;
    int hb   = blk % 3;          // head pair 0..2
    int win  = blk / 3;
    int wwin = win % NWIN;
    int wh = wwin / NWW;
    int ww = wwin % NWW;

    // ---- load: threads 0-127 load head 2*hb, threads 128-255 load head 2*hb+1 ----
    {
        int t   = tid & 127;
        int lh  = tid >> 7;
        const bf16* base = g_qkv + (size_t)win * Nwin * CQKV + (2 * hb + lh) * HD;
        for (int idx = t; idx < 196; idx += 128) {
            int row = idx >> 2;
            int c   = (idx & 3) * 8;
            const bf16* src = base + (size_t)row * CQKV + c;
            *(uint4*)&qk[lh][0][row][c] = *(const uint4*)(src);
            *(uint4*)&qk[lh][1][row][c] = *(const uint4*)(src + Cch);
            *(uint4*)&vs[lh][row][c]    = *(const uint4*)(src + 2 * Cch);
        }
        for (int idx = t; idx < 150; idx += 128) {
            int r  = 49 + idx / 10;
            int c4 = (idx % 10) * 4;
            uint2 z = make_uint2(0u, 0u);
            *(uint2*)&qk[lh][0][r][c4] = z;
            *(uint2*)&qk[lh][1][r][c4] = z;
            *(uint2*)&vs[lh][r][c4]    = z;
        }
        for (int idx = t; idx < 169; idx += 128)
            rpb[lh][idx] = rpb_table[idx * NHh + 2 * hb + lh];
        if (tid < Nwin) {
            int r = tid / WSz;
            int c = tid % WSz;
            int hs  = wh * WSz + r;
            int wsc = ww * WSz + c;
            int gh = hs  < Hdim - WSz ? 0 : (hs  < Hdim - SSz ? 1 : 2);
            int gw = wsc < Wdim - WSz ? 0 : (wsc < Wdim - SSz ? 1 : 2);
            grp[tid] = gh * 3 + gw;
        }
    }
    __syncthreads();

    // ---- QK^T : S(64x64) = Q(64x32) * K^T -----------------------------------------
    float c[8][4];
#pragma unroll
    for (int nt = 0; nt < 8; nt++)
#pragma unroll
        for (int e = 0; e < 4; e++) c[nt][e] = 0.f;
    {
        uint32_t a[2][4];
#pragma unroll
        for (int ksx = 0; ksx < 2; ksx++)
            ldsm_x4(a[ksx][0], a[ksx][1], a[ksx][2], a[ksx][3],
                    &qk[hh][0][m0 + (lane & 15)][ksx * 16 + (lane >> 4) * 8]);
#pragma unroll
        for (int jt = 0; jt < 4; jt++) {
#pragma unroll
            for (int ksx = 0; ksx < 2; ksx++) {
                uint32_t r0, r1, r2, r3;
                ldsm_x4(r0, r1, r2, r3,
                        &qk[hh][1][jt * 16 + (lane & 15)][ksx * 16 + (lane >> 4) * 8]);
                uint32_t b0[2];
                uint32_t b1[2];
                b0[0] = r0; b0[1] = r2;
                b1[0] = r1; b1[1] = r3;
                mma_bf16(c[jt * 2],     a[ksx], b0);
                mma_bf16(c[jt * 2 + 1], a[ksx], b1);
            }
        }
    }
    // all q/k reads complete before ps overwrites them
    __syncthreads();

    bf16* psp = &qk[hh][0][0][0];   // 64 rows x stride 72 (9216 elems <= 10240)

    // ---- register softmax ------------------------------------------------------------
    {
        const float scale = 0.1767766952966369f;
        int i0 = m0 + (lane >> 2);
        int i1 = i0 + 8;
        int ri0 = i0 / WSz, ci0 = i0 % WSz;
        int ri1 = i1 / WSz, ci1 = i1 % WSz;
        int v0ok = (i0 < Nwin);
        int v1ok = (i1 < Nwin);
        int gi0 = v0ok ? grp[i0] : 0;
        int gi1 = v1ok ? grp[i1] : 0;

#pragma unroll
        for (int nt = 0; nt < 8; nt++) {
#pragma unroll
            for (int e = 0; e < 2; e++) {
                int j = nt * 8 + (lane & 3) * 2 + e;
                if (j < Nwin) {
                    int rj = j / WSz;
                    int cj = j % WSz;
                    int gj = grp[j];
                    float b0 = rpb[hh][(ri0 - rj + 6) * 13 + (ci0 - cj + 6)];
                    float b1 = rpb[hh][(ri1 - rj + 6) * 13 + (ci1 - cj + 6)];
                    float s0 = c[nt][e] * scale + b0 + (gi0 != gj ? -100.f : 0.f);
                    float s1 = c[nt][2 + e] * scale + b1 + (gi1 != gj ? -100.f : 0.f);
                    c[nt][e]     = v0ok ? s0 : -1e30f;
                    c[nt][2 + e] = v1ok ? s1 : -1e30f;
                } else {
                    c[nt][e]     = -1e30f;
                    c[nt][2 + e] = -1e30f;
                }
            }
        }

        float mx0 = -1e30f;
        float mx1 = -1e30f;
#pragma unroll
        for (int nt = 0; nt < 8; nt++) {
            mx0 = fmaxf(mx0, fmaxf(c[nt][0], c[nt][1]));
            mx1 = fmaxf(mx1, fmaxf(c[nt][2], c[nt][3]));
        }
        mx0 = fmaxf(mx0, __shfl_xor_sync(0xffffffffu, mx0, 1));
        mx0 = fmaxf(mx0, __shfl_xor_sync(0xffffffffu, mx0, 2));
        mx1 = fmaxf(mx1, __shfl_xor_sync(0xffffffffu, mx1, 1));
        mx1 = fmaxf(mx1, __shfl_xor_sync(0xffffffffu, mx1, 2));

        float sm0 = 0.f;
        float sm1 = 0.f;
#pragma unroll
        for (int nt = 0; nt < 8; nt++) {
            c[nt][0] = __expf(c[nt][0] - mx0);
            c[nt][1] = __expf(c[nt][1] - mx0);
            c[nt][2] = __expf(c[nt][2] - mx1);
            c[nt][3] = __expf(c[nt][3] - mx1);
            sm0 += c[nt][0] + c[nt][1];
            sm1 += c[nt][2] + c[nt][3];
        }
        sm0 += __shfl_xor_sync(0xffffffffu, sm0, 1);
        sm0 += __shfl_xor_sync(0xffffffffu, sm0, 2);
        sm1 += __shfl_xor_sync(0xffffffffu, sm1, 1);
        sm1 += __shfl_xor_sync(0xffffffffu, sm1, 2);
        float inv0 = 1.f / sm0;
        float inv1 = 1.f / sm1;

        int j0 = (lane & 3) * 2;
#pragma unroll
        for (int nt = 0; nt < 8; nt++) {
            *(__nv_bfloat162*)&psp[i0 * 72 + nt * 8 + j0] =
                __halves2bfloat162(__float2bfloat16(c[nt][0] * inv0),
                                   __float2bfloat16(c[nt][1] * inv0));
            *(__nv_bfloat162*)&psp[i1 * 72 + nt * 8 + j0] =
                __halves2bfloat162(__float2bfloat16(c[nt][2] * inv1),
                                   __float2bfloat16(c[nt][3] * inv1));
        }
    }
    __syncthreads();

    // ---- O = P(64x64) * V(64x32) -------------------------------------------------------
    {
        float o[4][4];
#pragma unroll
        for (int nt = 0; nt < 4; nt++)
#pragma unroll
            for (int e = 0; e < 4; e++) o[nt][e] = 0.f;

#pragma unroll
        for (int ksx = 0; ksx < 4; ksx++) {
            uint32_t a[4];
            ldsm_x4(a[0], a[1], a[2], a[3],
                    &psp[(m0 + (lane & 15)) * 72 + ksx * 16 + (lane >> 4) * 8]);
#pragma unroll
            for (int bt = 0; bt < 2; bt++) {
                uint32_t r0, r1, r2, r3;
                ldsm_x4_t(r0, r1, r2, r3,
                          &vs[hh][ksx * 16 + (lane & 15)][bt * 16 + (lane >> 4) * 8]);
                uint32_t b0[2];
                uint32_t b1[2];
                b0[0] = r0; b0[1] = r1;
                b1[0] = r2; b1[1] = r3;
                mma_bf16(o[bt * 2],     a, b0);
                mma_bf16(o[bt * 2 + 1], a, b1);
            }
        }

        bf16* outw = g_att + (size_t)win * Nwin * Cch + (2 * hb + hh) * HD;
        int i0 = m0 + (lane >> 2);
#pragma unroll
        for (int nt = 0; nt < 4; nt++) {
            int d = nt * 8 + (lane & 3) * 2;
            if (i0 < Nwin) {
                *(__nv_bfloat162*)(outw + (size_t)i0 * Cch + d) =
                    __halves2bfloat162(__float2bfloat16(o[nt][0]), __float2bfloat16(o[nt][1]));
            }
            if (i0 + 8 < Nwin) {
                *(__nv_bfloat162*)(outw + (size_t)(i0 + 8) * Cch + d) =
                    __halves2bfloat162(__float2bfloat16(o[nt][2]), __float2bfloat16(o[nt][3]));
            }
        }
    }
}

// ---------------- launch ----------------------------------------------------------
extern "C" void kernel_launch(void* const* d_in, const int* in_sizes, int n_in,
                              void* d_out, int out_size)
{
    const float* x       = (const float*)d_in[0];
    const float* norm1_g = (const float*)d_in[1];
    const float* norm1_b = (const float*)d_in[2];
    const float* qkv_w   = (const float*)d_in[3];
    const float* qkv_b   = (const float*)d_in[4];
    const float* rpb_t   = (const float*)d_in[5];
    const float* proj_w  = (const float*)d_in[6];
    const float* proj_b  = (const float*)d_in[7];
    const float* norm2_g = (const float*)d_in[8];
    const float* norm2_b = (const float*)d_in[9];
    const float* fc1_w   = (const float*)d_in[10];
    const float* fc1_b   = (const float*)d_in[11];
    const float* fc2_w   = (const float*)d_in[12];
    const float* fc2_b   = (const float*)d_in[13];
    float* out = (float*)d_out;

    dim3 cvt_grid((NCVT + 255) / 256);
    cvt_all_kernel<<<cvt_grid, 256>>>(qkv_w, proj_w, fc1_w, fc2_w);

    dim3 ln_grid(TOK / 8);
    ln1_window_kernel<<<ln_grid, 256>>>(x, norm1_g, norm1_b);

    dim3 qkv_grid(CQKV / BN, TOK / BM);
    hgemm_qkv<<<qkv_grid, 256>>>(qkv_b);

    dim3 attn_grid((TOK / Nwin) * 3);
    attn_kernel<<<attn_grid, 256>>>(rpb_t);

    dim3 proj_grid(Cch / BN, TOK / BM);
    hgemm_proj<<<proj_grid, 256>>>(proj_b, out, x);

    ln2_kernel<<<ln_grid, 256>>>(out, norm2_g, norm2_b);

    dim3 fc1_grid(HID / BN, TOK / BM);
    hgemm_fc1<<<fc1_grid, 256>>>(fc1_b);

    dim3 fc2_grid(Cch / BN, TOK / BM);
    hgemm_fc2<<<fc2_grid, 256>>>(fc2_b, out);
}

// round 11
// speedup vs baseline: 1.0933x; 1.0123x over previous
#include <cuda_runtime.h>
#include <cuda_bf16.h>
#include <stdint.h>
#include <math.h>

#define Bv    8
#define Hdim  224
#define Wdim  224
#define Cch   192
#define NHh   6
#define HD    32
#define WSz   7
#define SSz   3
#define Nwin  49
#define NWH   32
#define NWW   32
#define NWIN  1024
#define Ltok  (Hdim*Wdim)
#define TOK   (Bv*Ltok)     // 401408
#define HID   768
#define CQKV  576

typedef __nv_bfloat16 bf16;

// ---------------- scratch (device globals) ------------------------------------
__device__ bf16 g_xw[(size_t)TOK * Cch];
__device__ bf16 g_qkv[(size_t)TOK * CQKV];
__device__ bf16 g_att[(size_t)TOK * Cch];
__device__ bf16 g_hid[(size_t)TOK * HID];
__device__ bf16 g_wqkv[Cch * CQKV];
__device__ bf16 g_wproj[Cch * Cch];
__device__ bf16 g_wfc1[Cch * HID];
__device__ bf16 g_wfc2[HID * Cch];

#define NQKV  (Cch*CQKV)
#define NPROJ (Cch*Cch)
#define NFC1  (Cch*HID)
#define NFC2  (HID*Cch)
#define NCVT  (NQKV+NPROJ+NFC1+NFC2)

// ---------------- fused weight fp32 -> bf16 -----------------------------------
__global__ void cvt_all_kernel(const float* __restrict__ qkv_w,
                               const float* __restrict__ proj_w,
                               const float* __restrict__ fc1_w,
                               const float* __restrict__ fc2_w)
{
    int i = blockIdx.x * 256 + threadIdx.x;
    if (i >= NCVT) return;
    if (i < NQKV) {
        g_wqkv[i] = __float2bfloat16(qkv_w[i]);
    } else if (i < NQKV + NPROJ) {
        int j = i - NQKV;
        g_wproj[j] = __float2bfloat16(proj_w[j]);
    } else if (i < NQKV + NPROJ + NFC1) {
        int j = i - NQKV - NPROJ;
        g_wfc1[j] = __float2bfloat16(fc1_w[j]);
    } else {
        int j = i - NQKV - NPROJ - NFC1;
        g_wfc2[j] = __float2bfloat16(fc2_w[j]);
    }
}

// ---------------- LN1 + shift + window-partition -------------------------------
__global__ void __launch_bounds__(256) ln1_window_kernel(
    const float* __restrict__ x, const float* __restrict__ g,
    const float* __restrict__ b)
{
    int warp = (blockIdx.x * blockDim.x + threadIdx.x) >> 5;
    int lane = threadIdx.x & 31;
    if (warp >= TOK) return;
    int bidx = warp / Ltok;
    int l    = warp % Ltok;
    const float* xr = x + (size_t)warp * Cch;
    float v[6];
    float s = 0.f;
    float ss = 0.f;
#pragma unroll
    for (int i = 0; i < 6; i++) {
        v[i] = xr[lane + 32 * i];
        s  += v[i];
        ss += v[i] * v[i];
    }
#pragma unroll
    for (int o = 16; o; o >>= 1) {
        s  += __shfl_xor_sync(0xffffffffu, s,  o);
        ss += __shfl_xor_sync(0xffffffffu, ss, o);
    }
    float mean = s * (1.f / Cch);
    float rstd = rsqrtf(ss * (1.f / Cch) - mean * mean + 1e-5f);

    int h = l / Wdim;
    int w = l % Wdim;
    int hs = h - SSz; if (hs < 0) hs += Hdim;
    int ws = w - SSz; if (ws < 0) ws += Wdim;
    int wh = hs / WSz;
    int r  = hs % WSz;
    int ww = ws / WSz;
    int c  = ws % WSz;
    int row = (bidx * NWIN + wh * NWW + ww) * Nwin + r * WSz + c;
    bf16* dst = g_xw + (size_t)row * Cch;
#pragma unroll
    for (int i = 0; i < 6; i++) {
        int ch = lane + 32 * i;
        dst[ch] = __float2bfloat16((v[i] - mean) * rstd * g[ch] + b[ch]);
    }
}

// ---------------- LN2 -----------------------------------------------------------
__global__ void __launch_bounds__(256) ln2_kernel(
    const float* __restrict__ x, const float* __restrict__ g,
    const float* __restrict__ b)
{
    int warp = (blockIdx.x * blockDim.x + threadIdx.x) >> 5;
    int lane = threadIdx.x & 31;
    if (warp >= TOK) return;
    const float* xr = x + (size_t)warp * Cch;
    float v[6];
    float s = 0.f;
    float ss = 0.f;
#pragma unroll
    for (int i = 0; i < 6; i++) {
        v[i] = xr[lane + 32 * i];
        s  += v[i];
        ss += v[i] * v[i];
    }
#pragma unroll
    for (int o = 16; o; o >>= 1) {
        s  += __shfl_xor_sync(0xffffffffu, s,  o);
        ss += __shfl_xor_sync(0xffffffffu, ss, o);
    }
    float mean = s * (1.f / Cch);
    float rstd = rsqrtf(ss * (1.f / Cch) - mean * mean + 1e-5f);
    bf16* dst = g_xw + (size_t)warp * Cch;
#pragma unroll
    for (int i = 0; i < 6; i++) {
        int ch = lane + 32 * i;
        dst[ch] = __float2bfloat16((v[i] - mean) * rstd * g[ch] + b[ch]);
    }
}

// ---------------- mma / ldmatrix helpers -----------------------------------------
__device__ __forceinline__ void ldsm_x4(uint32_t& r0, uint32_t& r1, uint32_t& r2,
                                        uint32_t& r3, const void* p)
{
    uint32_t a = (uint32_t)__cvta_generic_to_shared(p);
    asm volatile("ldmatrix.sync.aligned.m8n8.x4.shared.b16 {%0,%1,%2,%3},[%4];"
                 : "=r"(r0), "=r"(r1), "=r"(r2), "=r"(r3) : "r"(a));
}
__device__ __forceinline__ void ldsm_x4_t(uint32_t& r0, uint32_t& r1, uint32_t& r2,
                                          uint32_t& r3, const void* p)
{
    uint32_t a = (uint32_t)__cvta_generic_to_shared(p);
    asm volatile("ldmatrix.sync.aligned.m8n8.x4.trans.shared.b16 {%0,%1,%2,%3},[%4];"
                 : "=r"(r0), "=r"(r1), "=r"(r2), "=r"(r3) : "r"(a));
}
__device__ __forceinline__ void mma_bf16(float* c, const uint32_t* a, const uint32_t* b)
{
    asm volatile(
        "mma.sync.aligned.m16n8k16.row.col.f32.bf16.bf16.f32 "
        "{%0,%1,%2,%3},{%4,%5,%6,%7},{%8,%9},{%0,%1,%2,%3};"
        : "+f"(c[0]), "+f"(c[1]), "+f"(c[2]), "+f"(c[3])
        : "r"(a[0]), "r"(a[1]), "r"(a[2]), "r"(a[3]), "r"(b[0]), "r"(b[1]));
}
__device__ __forceinline__ void cp16(void* smem, const void* gmem)
{
    uint32_t a = (uint32_t)__cvta_generic_to_shared(smem);
    asm volatile("cp.async.cg.shared.global [%0], [%1], 16;" :: "r"(a), "l"(gmem));
}
__device__ __forceinline__ void cp_commit()
{
    asm volatile("cp.async.commit_group;" ::: "memory");
}
__device__ __forceinline__ void cp_wait_all()
{
    asm volatile("cp.async.wait_group 0;" ::: "memory");
}

// ---------------- bf16 tensor-core GEMM (BM=256, 8 warps x 32x64 strip) -----------
#define BM 256
#define BN 64
#define BK 32
#define ASTRIDE 40
#define BSTRIDE 72

// MODE 0: bf16 store (qkv)
// MODE 1: fp32 store, window-reverse + unshift + residual -> d_out
// MODE 2: exact GELU -> bf16 store (hidden)
// MODE 3: fp32 += (fc2 residual into d_out)
template <int MODE>
__device__ __forceinline__ void hgemm_body(
    const bf16* A, const bf16* Bw, const float* bias, void* Cout,
    int Kd, int Nd, const float* resid)
{
    __shared__ bf16 As[2][BM][ASTRIDE];
    __shared__ bf16 Bs[2][BK][BSTRIDE];

    int tid  = threadIdx.x;
    int warp = tid >> 5;
    int lane = tid & 31;
    int row0 = blockIdx.y * BM;
    int col0 = blockIdx.x * BN;

    float acc[2][8][4];
#pragma unroll
    for (int i = 0; i < 2; i++)
#pragma unroll
        for (int j = 0; j < 8; j++)
#pragma unroll
            for (int k = 0; k < 4; k++) acc[i][j][k] = 0.f;

    // A: 256 rows x 32 cols = 1024 16B chunks; 4 per thread
    int ra0 = tid >> 2;
    int ka0 = (tid & 3) * 8;
    // B: 32 rows x 64 cols = 256 chunks; 1 per thread
    int rb = tid >> 3;
    int kb = (tid & 7) * 8;

    const bf16* Ag0 = A + (size_t)(row0 + ra0) * Kd + ka0;
    const bf16* Ag1 = Ag0 + (size_t)64 * Kd;
    const bf16* Ag2 = Ag0 + (size_t)128 * Kd;
    const bf16* Ag3 = Ag0 + (size_t)192 * Kd;
    const bf16* Bg  = Bw + (size_t)rb * Nd + col0 + kb;

    cp16(&As[0][ra0][ka0],       Ag0);
    cp16(&As[0][ra0 + 64][ka0],  Ag1);
    cp16(&As[0][ra0 + 128][ka0], Ag2);
    cp16(&As[0][ra0 + 192][ka0], Ag3);
    cp16(&Bs[0][rb][kb],         Bg);
    cp_commit();

    int buf = 0;
    for (int k0 = 0; k0 < Kd; k0 += BK) {
        cp_wait_all();
        __syncthreads();
        if (k0 + BK < Kd) {
            int nb = buf ^ 1;
            cp16(&As[nb][ra0][ka0],       Ag0 + k0 + BK);
            cp16(&As[nb][ra0 + 64][ka0],  Ag1 + k0 + BK);
            cp16(&As[nb][ra0 + 128][ka0], Ag2 + k0 + BK);
            cp16(&As[nb][ra0 + 192][ka0], Ag3 + k0 + BK);
            cp16(&Bs[nb][rb][kb],         Bg + (size_t)(k0 + BK) * Nd);
            cp_commit();
        }

#pragma unroll
        for (int ks = 0; ks < 2; ks++) {
            uint32_t af[2][4];
            uint32_t bfr[8][2];
#pragma unroll
            for (int mt = 0; mt < 2; mt++)
                ldsm_x4(af[mt][0], af[mt][1], af[mt][2], af[mt][3],
                        &As[buf][warp * 32 + mt * 16 + (lane & 15)][ks * 16 + (lane >> 4) * 8]);
#pragma unroll
            for (int bt = 0; bt < 4; bt++) {
                uint32_t r0, r1, r2, r3;
                ldsm_x4_t(r0, r1, r2, r3,
                          &Bs[buf][ks * 16 + (lane & 15)][bt * 16 + (lane >> 4) * 8]);
                bfr[bt * 2][0] = r0;
                bfr[bt * 2][1] = r1;
                bfr[bt * 2 + 1][0] = r2;
                bfr[bt * 2 + 1][1] = r3;
            }
#pragma unroll
            for (int mt = 0; mt < 2; mt++)
#pragma unroll
                for (int nt = 0; nt < 8; nt++)
                    mma_bf16(acc[mt][nt], af[mt], bfr[nt]);
        }
        buf ^= 1;
    }

#pragma unroll
    for (int mt = 0; mt < 2; mt++) {
#pragma unroll
        for (int rh = 0; rh < 2; rh++) {
            int row = row0 + warp * 32 + mt * 16 + rh * 8 + (lane >> 2);
            size_t dstrow;
            if (MODE == 1) {
                int win = row / Nwin;
                int n = row % Nwin;
                int bb = win / NWIN;
                int w_ = win % NWIN;
                int wh = w_ / NWW;
                int ww = w_ % NWW;
                int h = wh * WSz + n / WSz + SSz; if (h >= Hdim) h -= Hdim;
                int w = ww * WSz + n % WSz + SSz; if (w >= Wdim) w -= Wdim;
                dstrow = ((size_t)bb * Ltok + h * Wdim + w) * Cch;
            } else {
                dstrow = (size_t)row * Nd;
            }
#pragma unroll
            for (int nt = 0; nt < 8; nt++) {
                int col = col0 + nt * 8 + (lane & 3) * 2;
                float v0 = acc[mt][nt][rh * 2 + 0] + bias[col];
                float v1 = acc[mt][nt][rh * 2 + 1] + bias[col + 1];
                if (MODE == 0) {
                    *(__nv_bfloat162*)((bf16*)Cout + dstrow + col) =
                        __halves2bfloat162(__float2bfloat16(v0), __float2bfloat16(v1));
                } else if (MODE == 2) {
                    float g0 = 0.5f * v0 * (1.f + erff(v0 * 0.7071067811865475f));
                    float g1 = 0.5f * v1 * (1.f + erff(v1 * 0.7071067811865475f));
                    *(__nv_bfloat162*)((bf16*)Cout + dstrow + col) =
                        __halves2bfloat162(__float2bfloat16(g0), __float2bfloat16(g1));
                } else if (MODE == 1) {
                    float* o = (float*)Cout + dstrow + col;
                    o[0] = resid[dstrow + col]     + v0;
                    o[1] = resid[dstrow + col + 1] + v1;
                } else {
                    float* o = (float*)Cout + dstrow + col;
                    o[0] += v0;
                    o[1] += v1;
                }
            }
        }
    }
}

// ---------------- concrete GEMM wrappers ------------------------------------------
__global__ void __launch_bounds__(256, 2) hgemm_qkv(const float* __restrict__ bias)
{
    hgemm_body<0>(g_xw, g_wqkv, bias, g_qkv, Cch, CQKV, (const float*)0);
}
__global__ void __launch_bounds__(256, 2) hgemm_proj(const float* __restrict__ bias,
                                                     float* __restrict__ out,
                                                     const float* __restrict__ resid)
{
    hgemm_body<1>(g_att, g_wproj, bias, out, Cch, Cch, resid);
}
__global__ void __launch_bounds__(256, 2) hgemm_fc1(const float* __restrict__ bias)
{
    hgemm_body<2>(g_xw, g_wfc1, bias, g_hid, Cch, HID, (const float*)0);
}
__global__ void __launch_bounds__(256, 2) hgemm_fc2(const float* __restrict__ bias,
                                                    float* __restrict__ out)
{
    hgemm_body<3>(g_hid, g_wfc2, bias, out, HID, Cch, (const float*)0);
}

// ---------------- windowed attention: 2 heads per block, HMMA + reg softmax --------
__global__ void __launch_bounds__(256) attn_kernel(const float* __restrict__ rpb_table)
{
    __shared__ bf16  qk[2][2][64][40];   // [head][0=q,1=k][row][col]; ps aliases this
    __shared__ bf16  vs[2][64][40];
    __shared__ float rpb[2][169];
    __shared__ int   grp[Nwin];

    int tid  = threadIdx.x;
    int warp = tid >> 5;
    int lane = tid & 31;
    int hh   = warp >> 2;
    int wg   = warp & 3;
    int m0   = wg * 16;

    int blk  = blockIdx.x;
    int hb   = blk % 3;
    int win  = blk / 3;
    int wwin = win % NWIN;
    int wh = wwin / NWW;
    int ww = wwin % NWW;

    {
        int t   = tid & 127;
        int lh  = tid >> 7;
        const bf16* base = g_qkv + (size_t)win * Nwin * CQKV + (2 * hb + lh) * HD;
        for (int idx = t; idx < 196; idx += 128) {
            int row = idx >> 2;
            int c   = (idx & 3) * 8;
            const bf16* src = base + (size_t)row * CQKV + c;
            *(uint4*)&qk[lh][0][row][c] = *(const uint4*)(src);
            *(uint4*)&qk[lh][1][row][c] = *(const uint4*)(src + Cch);
            *(uint4*)&vs[lh][row][c]    = *(const uint4*)(src + 2 * Cch);
        }
        for (int idx = t; idx < 150; idx += 128) {
            int r  = 49 + idx / 10;
            int c4 = (idx % 10) * 4;
            uint2 z = make_uint2(0u, 0u);
            *(uint2*)&qk[lh][0][r][c4] = z;
            *(uint2*)&qk[lh][1][r][c4] = z;
            *(uint2*)&vs[lh][r][c4]    = z;
        }
        for (int idx = t; idx < 169; idx += 128)
            rpb[lh][idx] = rpb_table[idx * NHh + 2 * hb + lh];
        if (tid < Nwin) {
            int r = tid / WSz;
            int c = tid % WSz;
            int hs  = wh * WSz + r;
            int wsc = ww * WSz + c;
            int gh = hs  < Hdim - WSz ? 0 : (hs  < Hdim - SSz ? 1 : 2);
            int gw = wsc < Wdim - WSz ? 0 : (wsc < Wdim - SSz ? 1 : 2);
            grp[tid] = gh * 3 + gw;
        }
    }
    __syncthreads();

    float c[8][4];
#pragma unroll
    for (int nt = 0; nt < 8; nt++)
#pragma unroll
        for (int e = 0; e < 4; e++) c[nt][e] = 0.f;
    {
        uint32_t a[2][4];
#pragma unroll
        for (int ksx = 0; ksx < 2; ksx++)
            ldsm_x4(a[ksx][0], a[ksx][1], a[ksx][2], a[ksx][3],
                    &qk[hh][0][m0 + (lane & 15)][ksx * 16 + (lane >> 4) * 8]);
#pragma unroll
        for (int jt = 0; jt < 4; jt++) {
#pragma unroll
            for (int ksx = 0; ksx < 2; ksx++) {
                uint32_t r0, r1, r2, r3;
                ldsm_x4(r0, r1, r2, r3,
                        &qk[hh][1][jt * 16 + (lane & 15)][ksx * 16 + (lane >> 4) * 8]);
                uint32_t b0[2];
                uint32_t b1[2];
                b0[0] = r0; b0[1] = r2;
                b1[0] = r1; b1[1] = r3;
                mma_bf16(c[jt * 2],     a[ksx], b0);
                mma_bf16(c[jt * 2 + 1], a[ksx], b1);
            }
        }
    }
    __syncthreads();

    bf16* psp = &qk[hh][0][0][0];

    {
        const float scale = 0.1767766952966369f;
        int i0 = m0 + (lane >> 2);
        int i1 = i0 + 8;
        int ri0 = i0 / WSz, ci0 = i0 % WSz;
        int ri1 = i1 / WSz, ci1 = i1 % WSz;
        int v0ok = (i0 < Nwin);
        int v1ok = (i1 < Nwin);
        int gi0 = v0ok ? grp[i0] : 0;
        int gi1 = v1ok ? grp[i1] : 0;

#pragma unroll
        for (int nt = 0; nt < 8; nt++) {
#pragma unroll
            for (int e = 0; e < 2; e++) {
                int j = nt * 8 + (lane & 3) * 2 + e;
                if (j < Nwin) {
                    int rj = j / WSz;
                    int cj = j % WSz;
                    int gj = grp[j];
                    float b0 = rpb[hh][(ri0 - rj + 6) * 13 + (ci0 - cj + 6)];
                    float b1 = rpb[hh][(ri1 - rj + 6) * 13 + (ci1 - cj + 6)];
                    float s0 = c[nt][e] * scale + b0 + (gi0 != gj ? -100.f : 0.f);
                    float s1 = c[nt][2 + e] * scale + b1 + (gi1 != gj ? -100.f : 0.f);
                    c[nt][e]     = v0ok ? s0 : -1e30f;
                    c[nt][2 + e] = v1ok ? s1 : -1e30f;
                } else {
                    c[nt][e]     = -1e30f;
                    c[nt][2 + e] = -1e30f;
                }
            }
        }

        float mx0 = -1e30f;
        float mx1 = -1e30f;
#pragma unroll
        for (int nt = 0; nt < 8; nt++) {
            mx0 = fmaxf(mx0, fmaxf(c[nt][0], c[nt][1]));
            mx1 = fmaxf(mx1, fmaxf(c[nt][2], c[nt][3]));
        }
        mx0 = fmaxf(mx0, __shfl_xor_sync(0xffffffffu, mx0, 1));
        mx0 = fmaxf(mx0, __shfl_xor_sync(0xffffffffu, mx0, 2));
        mx1 = fmaxf(mx1, __shfl_xor_sync(0xffffffffu, mx1, 1));
        mx1 = fmaxf(mx1, __shfl_xor_sync(0xffffffffu, mx1, 2));

        float sm0 = 0.f;
        float sm1 = 0.f;
#pragma unroll
        for (int nt = 0; nt < 8; nt++) {
            c[nt][0] = __expf(c[nt][0] - mx0);
            c[nt][1] = __expf(c[nt][1] - mx0);
            c[nt][2] = __expf(c[nt][2] - mx1);
            c[nt][3] = __expf(c[nt][3] - mx1);
            sm0 += c[nt][0] + c[nt][1];
            sm1 += c[nt][2] + c[nt][3];
        }
        sm0 += __shfl_xor_sync(0xffffffffu, sm0, 1);
        sm0 += __shfl_xor_sync(0xffffffffu, sm0, 2);
        sm1 += __shfl_xor_sync(0xffffffffu, sm1, 1);
        sm1 += __shfl_xor_sync(0xffffffffu, sm1, 2);
        float inv0 = 1.f / sm0;
        float inv1 = 1.f / sm1;

        int j0 = (lane & 3) * 2;
#pragma unroll
        for (int nt = 0; nt < 8; nt++) {
            *(__nv_bfloat162*)&psp[i0 * 72 + nt * 8 + j0] =
                __halves2bfloat162(__float2bfloat16(c[nt][0] * inv0),
                                   __float2bfloat16(c[nt][1] * inv0));
            *(__nv_bfloat162*)&psp[i1 * 72 + nt * 8 + j0] =
                __halves2bfloat162(__float2bfloat16(c[nt][2] * inv1),
                                   __float2bfloat16(c[nt][3] * inv1));
        }
    }
    __syncthreads();

    {
        float o[4][4];
#pragma unroll
        for (int nt = 0; nt < 4; nt++)
#pragma unroll
            for (int e = 0; e < 4; e++) o[nt][e] = 0.f;

#pragma unroll
        for (int ksx = 0; ksx < 4; ksx++) {
            uint32_t a[4];
            ldsm_x4(a[0], a[1], a[2], a[3],
                    &psp[(m0 + (lane & 15)) * 72 + ksx * 16 + (lane >> 4) * 8]);
#pragma unroll
            for (int bt = 0; bt < 2; bt++) {
                uint32_t r0, r1, r2, r3;
                ldsm_x4_t(r0, r1, r2, r3,
                          &vs[hh][ksx * 16 + (lane & 15)][bt * 16 + (lane >> 4) * 8]);
                uint32_t b0[2];
                uint32_t b1[2];
                b0[0] = r0; b0[1] = r1;
                b1[0] = r2; b1[1] = r3;
                mma_bf16(o[bt * 2],     a, b0);
                mma_bf16(o[bt * 2 + 1], a, b1);
            }
        }

        bf16* outw = g_att + (size_t)win * Nwin * Cch + (2 * hb + hh) * HD;
        int i0 = m0 + (lane >> 2);
#pragma unroll
        for (int nt = 0; nt < 4; nt++) {
            int d = nt * 8 + (lane & 3) * 2;
            if (i0 < Nwin) {
                *(__nv_bfloat162*)(outw + (size_t)i0 * Cch + d) =
                    __halves2bfloat162(__float2bfloat16(o[nt][0]), __float2bfloat16(o[nt][1]));
            }
            if (i0 + 8 < Nwin) {
                *(__nv_bfloat162*)(outw + (size_t)(i0 + 8) * Cch + d) =
                    __halves2bfloat162(__float2bfloat16(o[nt][2]), __float2bfloat16(o[nt][3]));
            }
        }
    }
}

// ---------------- launch ----------------------------------------------------------
extern "C" void kernel_launch(void* const* d_in, const int* in_sizes, int n_in,
                              void* d_out, int out_size)
{
    const float* x       = (const float*)d_in[0];
    const float* norm1_g = (const float*)d_in[1];
    const float* norm1_b = (const float*)d_in[2];
    const float* qkv_w   = (const float*)d_in[3];
    const float* qkv_b   = (const float*)d_in[4];
    const float* rpb_t   = (const float*)d_in[5];
    const float* proj_w  = (const float*)d_in[6];
    const float* proj_b  = (const float*)d_in[7];
    const float* norm2_g = (const float*)d_in[8];
    const float* norm2_b = (const float*)d_in[9];
    const float* fc1_w   = (const float*)d_in[10];
    const float* fc1_b   = (const float*)d_in[11];
    const float* fc2_w   = (const float*)d_in[12];
    const float* fc2_b   = (const float*)d_in[13];
    float* out = (float*)d_out;

    dim3 cvt_grid((NCVT + 255) / 256);
    cvt_all_kernel<<<cvt_grid, 256>>>(qkv_w, proj_w, fc1_w, fc2_w);

    dim3 ln_grid(TOK / 8);
    ln1_window_kernel<<<ln_grid, 256>>>(x, norm1_g, norm1_b);

    dim3 qkv_grid(CQKV / BN, TOK / BM);
    hgemm_qkv<<<qkv_grid, 256>>>(qkv_b);

    dim3 attn_grid((TOK / Nwin) * 3);
    attn_kernel<<<attn_grid, 256>>>(rpb_t);

    dim3 proj_grid(Cch / BN, TOK / BM);
    hgemm_proj<<<proj_grid, 256>>>(proj_b, out, x);

    ln2_kernel<<<ln_grid, 256>>>(out, norm2_g, norm2_b);

    dim3 fc1_grid(HID / BN, TOK / BM);
    hgemm_fc1<<<fc1_grid, 256>>>(fc1_b);

    dim3 fc2_grid(Cch / BN, TOK / BM);
    hgemm_fc2<<<fc2_grid, 256>>>(fc2_b, out);
}

// round 12
// speedup vs baseline: 1.0986x; 1.0049x over previous
#include <cuda_runtime.h>
#include <cuda_bf16.h>
#include <stdint.h>
#include <math.h>

#define Bv    8
#define Hdim  224
#define Wdim  224
#define Cch   192
#define NHh   6
#define HD    32
#define WSz   7
#define SSz   3
#define Nwin  49
#define NWH   32
#define NWW   32
#define NWIN  1024
#define Ltok  (Hdim*Wdim)
#define TOK   (Bv*Ltok)     // 401408
#define HID   768
#define CQKV  576
#define WINTILE (Nwin*HD)   // 1568 elems per (win,sel,head) tile

typedef __nv_bfloat16 bf16;

// ---------------- scratch (device globals) ------------------------------------
__device__ bf16 g_xw[(size_t)TOK * Cch];
__device__ bf16 g_qkv[(size_t)TOK * CQKV];   // head-major: [win][sel][head][n][d]
__device__ bf16 g_att[(size_t)TOK * Cch];
__device__ bf16 g_hid[(size_t)TOK * HID];
__device__ bf16 g_wqkv[Cch * CQKV];
__device__ bf16 g_wproj[Cch * Cch];
__device__ bf16 g_wfc1[Cch * HID];
__device__ bf16 g_wfc2[HID * Cch];

#define NQKV  (Cch*CQKV)
#define NPROJ (Cch*Cch)
#define NFC1  (Cch*HID)
#define NFC2  (HID*Cch)
#define NCVT  (NQKV+NPROJ+NFC1+NFC2)

// ---------------- fused weight fp32 -> bf16 -----------------------------------
__global__ void cvt_all_kernel(const float* __restrict__ qkv_w,
                               const float* __restrict__ proj_w,
                               const float* __restrict__ fc1_w,
                               const float* __restrict__ fc2_w)
{
    int i = blockIdx.x * 256 + threadIdx.x;
    if (i >= NCVT) return;
    if (i < NQKV) {
        g_wqkv[i] = __float2bfloat16(qkv_w[i]);
    } else if (i < NQKV + NPROJ) {
        int j = i - NQKV;
        g_wproj[j] = __float2bfloat16(proj_w[j]);
    } else if (i < NQKV + NPROJ + NFC1) {
        int j = i - NQKV - NPROJ;
        g_wfc1[j] = __float2bfloat16(fc1_w[j]);
    } else {
        int j = i - NQKV - NPROJ - NFC1;
        g_wfc2[j] = __float2bfloat16(fc2_w[j]);
    }
}

// ---------------- LN1 + shift + window-partition -------------------------------
__global__ void __launch_bounds__(256) ln1_window_kernel(
    const float* __restrict__ x, const float* __restrict__ g,
    const float* __restrict__ b)
{
    int warp = (blockIdx.x * blockDim.x + threadIdx.x) >> 5;
    int lane = threadIdx.x & 31;
    if (warp >= TOK) return;
    int bidx = warp / Ltok;
    int l    = warp % Ltok;
    const float* xr = x + (size_t)warp * Cch;
    float v[6];
    float s = 0.f;
    float ss = 0.f;
#pragma unroll
    for (int i = 0; i < 6; i++) {
        v[i] = xr[lane + 32 * i];
        s  += v[i];
        ss += v[i] * v[i];
    }
#pragma unroll
    for (int o = 16; o; o >>= 1) {
        s  += __shfl_xor_sync(0xffffffffu, s,  o);
        ss += __shfl_xor_sync(0xffffffffu, ss, o);
    }
    float mean = s * (1.f / Cch);
    float rstd = rsqrtf(ss * (1.f / Cch) - mean * mean + 1e-5f);

    int h = l / Wdim;
    int w = l % Wdim;
    int hs = h - SSz; if (hs < 0) hs += Hdim;
    int ws = w - SSz; if (ws < 0) ws += Wdim;
    int wh = hs / WSz;
    int r  = hs % WSz;
    int ww = ws / WSz;
    int c  = ws % WSz;
    int row = (bidx * NWIN + wh * NWW + ww) * Nwin + r * WSz + c;
    bf16* dst = g_xw + (size_t)row * Cch;
#pragma unroll
    for (int i = 0; i < 6; i++) {
        int ch = lane + 32 * i;
        dst[ch] = __float2bfloat16((v[i] - mean) * rstd * g[ch] + b[ch]);
    }
}

// ---------------- LN2 -----------------------------------------------------------
__global__ void __launch_bounds__(256) ln2_kernel(
    const float* __restrict__ x, const float* __restrict__ g,
    const float* __restrict__ b)
{
    int warp = (blockIdx.x * blockDim.x + threadIdx.x) >> 5;
    int lane = threadIdx.x & 31;
    if (warp >= TOK) return;
    const float* xr = x + (size_t)warp * Cch;
    float v[6];
    float s = 0.f;
    float ss = 0.f;
#pragma unroll
    for (int i = 0; i < 6; i++) {
        v[i] = xr[lane + 32 * i];
        s  += v[i];
        ss += v[i] * v[i];
    }
#pragma unroll
    for (int o = 16; o; o >>= 1) {
        s  += __shfl_xor_sync(0xffffffffu, s,  o);
        ss += __shfl_xor_sync(0xffffffffu, ss, o);
    }
    float mean = s * (1.f / Cch);
    float rstd = rsqrtf(ss * (1.f / Cch) - mean * mean + 1e-5f);
    bf16* dst = g_xw + (size_t)warp * Cch;
#pragma unroll
    for (int i = 0; i < 6; i++) {
        int ch = lane + 32 * i;
        dst[ch] = __float2bfloat16((v[i] - mean) * rstd * g[ch] + b[ch]);
    }
}

// ---------------- mma / ldmatrix helpers -----------------------------------------
__device__ __forceinline__ void ldsm_x4(uint32_t& r0, uint32_t& r1, uint32_t& r2,
                                        uint32_t& r3, const void* p)
{
    uint32_t a = (uint32_t)__cvta_generic_to_shared(p);
    asm volatile("ldmatrix.sync.aligned.m8n8.x4.shared.b16 {%0,%1,%2,%3},[%4];"
                 : "=r"(r0), "=r"(r1), "=r"(r2), "=r"(r3) : "r"(a));
}
__device__ __forceinline__ void ldsm_x4_t(uint32_t& r0, uint32_t& r1, uint32_t& r2,
                                          uint32_t& r3, const void* p)
{
    uint32_t a = (uint32_t)__cvta_generic_to_shared(p);
    asm volatile("ldmatrix.sync.aligned.m8n8.x4.trans.shared.b16 {%0,%1,%2,%3},[%4];"
                 : "=r"(r0), "=r"(r1), "=r"(r2), "=r"(r3) : "r"(a));
}
__device__ __forceinline__ void mma_bf16(float* c, const uint32_t* a, const uint32_t* b)
{
    asm volatile(
        "mma.sync.aligned.m16n8k16.row.col.f32.bf16.bf16.f32 "
        "{%0,%1,%2,%3},{%4,%5,%6,%7},{%8,%9},{%0,%1,%2,%3};"
        : "+f"(c[0]), "+f"(c[1]), "+f"(c[2]), "+f"(c[3])
        : "r"(a[0]), "r"(a[1]), "r"(a[2]), "r"(a[3]), "r"(b[0]), "r"(b[1]));
}
__device__ __forceinline__ void cp16(void* smem, const void* gmem)
{
    uint32_t a = (uint32_t)__cvta_generic_to_shared(smem);
    asm volatile("cp.async.cg.shared.global [%0], [%1], 16;" :: "r"(a), "l"(gmem));
}
__device__ __forceinline__ void cp_commit()
{
    asm volatile("cp.async.commit_group;" ::: "memory");
}
__device__ __forceinline__ void cp_wait_all()
{
    asm volatile("cp.async.wait_group 0;" ::: "memory");
}

// ---------------- bf16 tensor-core GEMM (BM=256, 8 warps x 32x64 strip) -----------
#define BM 256
#define BN 64
#define BK 32
#define ASTRIDE 40
#define BSTRIDE 72

// MODE 0: bf16 store scattered to head-major qkv layout
// MODE 1: fp32 store, window-reverse + unshift + residual -> d_out
// MODE 2: exact GELU -> bf16 store (hidden)
// MODE 3: fp32 += (fc2 residual into d_out)
template <int MODE>
__device__ __forceinline__ void hgemm_body(
    const bf16* A, const bf16* Bw, const float* bias, void* Cout,
    int Kd, int Nd, const float* resid)
{
    __shared__ bf16 As[2][BM][ASTRIDE];
    __shared__ bf16 Bs[2][BK][BSTRIDE];

    int tid  = threadIdx.x;
    int warp = tid >> 5;
    int lane = tid & 31;
    int row0 = blockIdx.y * BM;
    int col0 = blockIdx.x * BN;

    float acc[2][8][4];
#pragma unroll
    for (int i = 0; i < 2; i++)
#pragma unroll
        for (int j = 0; j < 8; j++)
#pragma unroll
            for (int k = 0; k < 4; k++) acc[i][j][k] = 0.f;

    int ra0 = tid >> 2;
    int ka0 = (tid & 3) * 8;
    int rb = tid >> 3;
    int kb = (tid & 7) * 8;

    const bf16* Ag0 = A + (size_t)(row0 + ra0) * Kd + ka0;
    const bf16* Ag1 = Ag0 + (size_t)64 * Kd;
    const bf16* Ag2 = Ag0 + (size_t)128 * Kd;
    const bf16* Ag3 = Ag0 + (size_t)192 * Kd;
    const bf16* Bg  = Bw + (size_t)rb * Nd + col0 + kb;

    cp16(&As[0][ra0][ka0],       Ag0);
    cp16(&As[0][ra0 + 64][ka0],  Ag1);
    cp16(&As[0][ra0 + 128][ka0], Ag2);
    cp16(&As[0][ra0 + 192][ka0], Ag3);
    cp16(&Bs[0][rb][kb],         Bg);
    cp_commit();

    int buf = 0;
    for (int k0 = 0; k0 < Kd; k0 += BK) {
        cp_wait_all();
        __syncthreads();
        if (k0 + BK < Kd) {
            int nb = buf ^ 1;
            cp16(&As[nb][ra0][ka0],       Ag0 + k0 + BK);
            cp16(&As[nb][ra0 + 64][ka0],  Ag1 + k0 + BK);
            cp16(&As[nb][ra0 + 128][ka0], Ag2 + k0 + BK);
            cp16(&As[nb][ra0 + 192][ka0], Ag3 + k0 + BK);
            cp16(&Bs[nb][rb][kb],         Bg + (size_t)(k0 + BK) * Nd);
            cp_commit();
        }

#pragma unroll
        for (int ks = 0; ks < 2; ks++) {
            uint32_t af[2][4];
            uint32_t bfr[8][2];
#pragma unroll
            for (int mt = 0; mt < 2; mt++)
                ldsm_x4(af[mt][0], af[mt][1], af[mt][2], af[mt][3],
                        &As[buf][warp * 32 + mt * 16 + (lane & 15)][ks * 16 + (lane >> 4) * 8]);
#pragma unroll
            for (int bt = 0; bt < 4; bt++) {
                uint32_t r0, r1, r2, r3;
                ldsm_x4_t(r0, r1, r2, r3,
                          &Bs[buf][ks * 16 + (lane & 15)][bt * 16 + (lane >> 4) * 8]);
                bfr[bt * 2][0] = r0;
                bfr[bt * 2][1] = r1;
                bfr[bt * 2 + 1][0] = r2;
                bfr[bt * 2 + 1][1] = r3;
            }
#pragma unroll
            for (int mt = 0; mt < 2; mt++)
#pragma unroll
                for (int nt = 0; nt < 8; nt++)
                    mma_bf16(acc[mt][nt], af[mt], bfr[nt]);
        }
        buf ^= 1;
    }

#pragma unroll
    for (int mt = 0; mt < 2; mt++) {
#pragma unroll
        for (int rh = 0; rh < 2; rh++) {
            int row = row0 + warp * 32 + mt * 16 + rh * 8 + (lane >> 2);
            size_t dstrow = 0;
            int winq = 0;
            int nq = 0;
            if (MODE == 1) {
                int win = row / Nwin;
                int n = row % Nwin;
                int bb = win / NWIN;
                int w_ = win % NWIN;
                int wh = w_ / NWW;
                int ww = w_ % NWW;
                int h = wh * WSz + n / WSz + SSz; if (h >= Hdim) h -= Hdim;
                int w = ww * WSz + n % WSz + SSz; if (w >= Wdim) w -= Wdim;
                dstrow = ((size_t)bb * Ltok + h * Wdim + w) * Cch;
            } else if (MODE == 0) {
                winq = row / Nwin;
                nq   = row % Nwin;
            } else {
                dstrow = (size_t)row * Nd;
            }
#pragma unroll
            for (int nt = 0; nt < 8; nt++) {
                int col = col0 + nt * 8 + (lane & 3) * 2;
                float v0 = acc[mt][nt][rh * 2 + 0] + bias[col];
                float v1 = acc[mt][nt][rh * 2 + 1] + bias[col + 1];
                if (MODE == 0) {
                    // head-major scatter: [win][sel][head][n][d]
                    int sel = col / Cch;
                    int hd2 = (col % Cch) >> 5;
                    int d   = col & 31;
                    size_t off = (((size_t)winq * 3 + sel) * NHh + hd2) * WINTILE
                               + nq * HD + d;
                    *(__nv_bfloat162*)((bf16*)Cout + off) =
                        __halves2bfloat162(__float2bfloat16(v0), __float2bfloat16(v1));
                } else if (MODE == 2) {
                    float g0 = 0.5f * v0 * (1.f + erff(v0 * 0.7071067811865475f));
                    float g1 = 0.5f * v1 * (1.f + erff(v1 * 0.7071067811865475f));
                    *(__nv_bfloat162*)((bf16*)Cout + dstrow + col) =
                        __halves2bfloat162(__float2bfloat16(g0), __float2bfloat16(g1));
                } else if (MODE == 1) {
                    float* o = (float*)Cout + dstrow + col;
                    o[0] = resid[dstrow + col]     + v0;
                    o[1] = resid[dstrow + col + 1] + v1;
                } else {
                    float* o = (float*)Cout + dstrow + col;
                    o[0] += v0;
                    o[1] += v1;
                }
            }
        }
    }
}

// ---------------- concrete GEMM wrappers ------------------------------------------
__global__ void __launch_bounds__(256, 2) hgemm_qkv(const float* __restrict__ bias)
{
    hgemm_body<0>(g_xw, g_wqkv, bias, g_qkv, Cch, CQKV, (const float*)0);
}
__global__ void __launch_bounds__(256, 2) hgemm_proj(const float* __restrict__ bias,
                                                     float* __restrict__ out,
                                                     const float* __restrict__ resid)
{
    hgemm_body<1>(g_att, g_wproj, bias, out, Cch, Cch, resid);
}
__global__ void __launch_bounds__(256, 2) hgemm_fc1(const float* __restrict__ bias)
{
    hgemm_body<2>(g_xw, g_wfc1, bias, g_hid, Cch, HID, (const float*)0);
}
__global__ void __launch_bounds__(256, 2) hgemm_fc2(const float* __restrict__ bias,
                                                    float* __restrict__ out)
{
    hgemm_body<3>(g_hid, g_wfc2, bias, out, HID, Cch, (const float*)0);
}

// ---------------- windowed attention: 2 heads/block, head-major streaming loads ----
__global__ void __launch_bounds__(256) attn_kernel(const float* __restrict__ rpb_table)
{
    __shared__ bf16  qk[2][2][64][40];   // [head][0=q,1=k][row][col]; ps aliases this
    __shared__ bf16  vs[2][64][40];
    __shared__ float rpb[2][169];
    __shared__ int   grp[Nwin];

    int tid  = threadIdx.x;
    int warp = tid >> 5;
    int lane = tid & 31;
    int hh   = warp >> 2;
    int wg   = warp & 3;
    int m0   = wg * 16;

    int blk  = blockIdx.x;
    int hb   = blk % 3;
    int win  = blk / 3;
    int wwin = win % NWIN;
    int wh = wwin / NWW;
    int ww = wwin % NWW;

    {
        int t   = tid & 127;
        int lh  = tid >> 7;
        int head = 2 * hb + lh;
        const bf16* bq = g_qkv + (((size_t)win * 3 + 0) * NHh + head) * WINTILE;
        const bf16* bk = g_qkv + (((size_t)win * 3 + 1) * NHh + head) * WINTILE;
        const bf16* bv = g_qkv + (((size_t)win * 3 + 2) * NHh + head) * WINTILE;
        for (int idx = t; idx < 196; idx += 128) {
            int row = idx >> 2;
            int c   = (idx & 3) * 8;
            *(uint4*)&qk[lh][0][row][c] = *(const uint4*)(bq + idx * 8);
            *(uint4*)&qk[lh][1][row][c] = *(const uint4*)(bk + idx * 8);
            *(uint4*)&vs[lh][row][c]    = *(const uint4*)(bv + idx * 8);
        }
        for (int idx = t; idx < 150; idx += 128) {
            int r  = 49 + idx / 10;
            int c4 = (idx % 10) * 4;
            uint2 z = make_uint2(0u, 0u);
            *(uint2*)&qk[lh][0][r][c4] = z;
            *(uint2*)&qk[lh][1][r][c4] = z;
            *(uint2*)&vs[lh][r][c4]    = z;
        }
        for (int idx = t; idx < 169; idx += 128)
            rpb[lh][idx] = rpb_table[idx * NHh + head];
        if (tid < Nwin) {
            int r = tid / WSz;
            int c = tid % WSz;
            int hs  = wh * WSz + r;
            int wsc = ww * WSz + c;
            int gh = hs  < Hdim - WSz ? 0 : (hs  < Hdim - SSz ? 1 : 2);
            int gw = wsc < Wdim - WSz ? 0 : (wsc < Wdim - SSz ? 1 : 2);
            grp[tid] = gh * 3 + gw;
        }
    }
    __syncthreads();

    float c[8][4];
#pragma unroll
    for (int nt = 0; nt < 8; nt++)
#pragma unroll
        for (int e = 0; e < 4; e++) c[nt][e] = 0.f;
    {
        uint32_t a[2][4];
#pragma unroll
        for (int ksx = 0; ksx < 2; ksx++)
            ldsm_x4(a[ksx][0], a[ksx][1], a[ksx][2], a[ksx][3],
                    &qk[hh][0][m0 + (lane & 15)][ksx * 16 + (lane >> 4) * 8]);
#pragma unroll
        for (int jt = 0; jt < 4; jt++) {
#pragma unroll
            for (int ksx = 0; ksx < 2; ksx++) {
                uint32_t r0, r1, r2, r3;
                ldsm_x4(r0, r1, r2, r3,
                        &qk[hh][1][jt * 16 + (lane & 15)][ksx * 16 + (lane >> 4) * 8]);
                uint32_t b0[2];
                uint32_t b1[2];
                b0[0] = r0; b0[1] = r2;
                b1[0] = r1; b1[1] = r3;
                mma_bf16(c[jt * 2],     a[ksx], b0);
                mma_bf16(c[jt * 2 + 1], a[ksx], b1);
            }
        }
    }
    __syncthreads();

    bf16* psp = &qk[hh][0][0][0];

    {
        const float scale = 0.1767766952966369f;
        int i0 = m0 + (lane >> 2);
        int i1 = i0 + 8;
        int ri0 = i0 / WSz, ci0 = i0 % WSz;
        int ri1 = i1 / WSz, ci1 = i1 % WSz;
        int v0ok = (i0 < Nwin);
        int v1ok = (i1 < Nwin);
        int gi0 = v0ok ? grp[i0] : 0;
        int gi1 = v1ok ? grp[i1] : 0;

#pragma unroll
        for (int nt = 0; nt < 8; nt++) {
#pragma unroll
            for (int e = 0; e < 2; e++) {
                int j = nt * 8 + (lane & 3) * 2 + e;
                if (j < Nwin) {
                    int rj = j / WSz;
                    int cj = j % WSz;
                    int gj = grp[j];
                    float b0 = rpb[hh][(ri0 - rj + 6) * 13 + (ci0 - cj + 6)];
                    float b1 = rpb[hh][(ri1 - rj + 6) * 13 + (ci1 - cj + 6)];
                    float s0 = c[nt][e] * scale + b0 + (gi0 != gj ? -100.f : 0.f);
                    float s1 = c[nt][2 + e] * scale + b1 + (gi1 != gj ? -100.f : 0.f);
                    c[nt][e]     = v0ok ? s0 : -1e30f;
                    c[nt][2 + e] = v1ok ? s1 : -1e30f;
                } else {
                    c[nt][e]     = -1e30f;
                    c[nt][2 + e] = -1e30f;
                }
            }
        }

        float mx0 = -1e30f;
        float mx1 = -1e30f;
#pragma unroll
        for (int nt = 0; nt < 8; nt++) {
            mx0 = fmaxf(mx0, fmaxf(c[nt][0], c[nt][1]));
            mx1 = fmaxf(mx1, fmaxf(c[nt][2], c[nt][3]));
        }
        mx0 = fmaxf(mx0, __shfl_xor_sync(0xffffffffu, mx0, 1));
        mx0 = fmaxf(mx0, __shfl_xor_sync(0xffffffffu, mx0, 2));
        mx1 = fmaxf(mx1, __shfl_xor_sync(0xffffffffu, mx1, 1));
        mx1 = fmaxf(mx1, __shfl_xor_sync(0xffffffffu, mx1, 2));

        float sm0 = 0.f;
        float sm1 = 0.f;
#pragma unroll
        for (int nt = 0; nt < 8; nt++) {
            c[nt][0] = __expf(c[nt][0] - mx0);
            c[nt][1] = __expf(c[nt][1] - mx0);
            c[nt][2] = __expf(c[nt][2] - mx1);
            c[nt][3] = __expf(c[nt][3] - mx1);
            sm0 += c[nt][0] + c[nt][1];
            sm1 += c[nt][2] + c[nt][3];
        }
        sm0 += __shfl_xor_sync(0xffffffffu, sm0, 1);
        sm0 += __shfl_xor_sync(0xffffffffu, sm0, 2);
        sm1 += __shfl_xor_sync(0xffffffffu, sm1, 1);
        sm1 += __shfl_xor_sync(0xffffffffu, sm1, 2);
        float inv0 = 1.f / sm0;
        float inv1 = 1.f / sm1;

        int j0 = (lane & 3) * 2;
#pragma unroll
        for (int nt = 0; nt < 8; nt++) {
            *(__nv_bfloat162*)&psp[i0 * 72 + nt * 8 + j0] =
                __halves2bfloat162(__float2bfloat16(c[nt][0] * inv0),
                                   __float2bfloat16(c[nt][1] * inv0));
            *(__nv_bfloat162*)&psp[i1 * 72 + nt * 8 + j0] =
                __halves2bfloat162(__float2bfloat16(c[nt][2] * inv1),
                                   __float2bfloat16(c[nt][3] * inv1));
        }
    }
    __syncthreads();

    {
        float o[4][4];
#pragma unroll
        for (int nt = 0; nt < 4; nt++)
#pragma unroll
            for (int e = 0; e < 4; e++) o[nt][e] = 0.f;

#pragma unroll
        for (int ksx = 0; ksx < 4; ksx++) {
            uint32_t a[4];
            ldsm_x4(a[0], a[1], a[2], a[3],
                    &psp[(m0 + (lane & 15)) * 72 + ksx * 16 + (lane >> 4) * 8]);
#pragma unroll
            for (int bt = 0; bt < 2; bt++) {
                uint32_t r0, r1, r2, r3;
                ldsm_x4_t(r0, r1, r2, r3,
                          &vs[hh][ksx * 16 + (lane & 15)][bt * 16 + (lane >> 4) * 8]);
                uint32_t b0[2];
                uint32_t b1[2];
                b0[0] = r0; b0[1] = r1;
                b1[0] = r2; b1[1] = r3;
                mma_bf16(o[bt * 2],     a, b0);
                mma_bf16(o[bt * 2 + 1], a, b1);
            }
        }

        bf16* outw = g_att + (size_t)win * Nwin * Cch + (2 * hb + hh) * HD;
        int i0 = m0 + (lane >> 2);
#pragma unroll
        for (int nt = 0; nt < 4; nt++) {
            int d = nt * 8 + (lane & 3) * 2;
            if (i0 < Nwin) {
                *(__nv_bfloat162*)(outw + (size_t)i0 * Cch + d) =
                    __halves2bfloat162(__float2bfloat16(o[nt][0]), __float2bfloat16(o[nt][1]));
            }
            if (i0 + 8 < Nwin) {
                *(__nv_bfloat162*)(outw + (size_t)(i0 + 8) * Cch + d) =
                    __halves2bfloat162(__float2bfloat16(o[nt][2]), __float2bfloat16(o[nt][3]));
            }
        }
    }
}

// ---------------- launch ----------------------------------------------------------
extern "C" void kernel_launch(void* const* d_in, const int* in_sizes, int n_in,
                              void* d_out, int out_size)
{
    const float* x       = (const float*)d_in[0];
    const float* norm1_g = (const float*)d_in[1];
    const float* norm1_b = (const float*)d_in[2];
    const float* qkv_w   = (const float*)d_in[3];
    const float* qkv_b   = (const float*)d_in[4];
    const float* rpb_t   = (const float*)d_in[5];
    const float* proj_w  = (const float*)d_in[6];
    const float* proj_b  = (const float*)d_in[7];
    const float* norm2_g = (const float*)d_in[8];
    const float* norm2_b = (const float*)d_in[9];
    const float* fc1_w   = (const float*)d_in[10];
    const float* fc1_b   = (const float*)d_in[11];
    const float* fc2_w   = (const float*)d_in[12];
    const float* fc2_b   = (const float*)d_in[13];
    float* out = (float*)d_out;

    dim3 cvt_grid((NCVT + 255) / 256);
    cvt_all_kernel<<<cvt_grid, 256>>>(qkv_w, proj_w, fc1_w, fc2_w);

    dim3 ln_grid(TOK / 8);
    ln1_window_kernel<<<ln_grid, 256>>>(x, norm1_g, norm1_b);

    dim3 qkv_grid(CQKV / BN, TOK / BM);
    hgemm_qkv<<<qkv_grid, 256>>>(qkv_b);

    dim3 attn_grid((TOK / Nwin) * 3);
    attn_kernel<<<attn_grid, 256>>>(rpb_t);

    dim3 proj_grid(Cch / BN, TOK / BM);
    hgemm_proj<<<proj_grid, 256>>>(proj_b, out, x);

    ln2_kernel<<<ln_grid, 256>>>(out, norm2_g, norm2_b);

    dim3 fc1_grid(HID / BN, TOK / BM);
    hgemm_fc1<<<fc1_grid, 256>>>(fc1_b);

    dim3 fc2_grid(Cch / BN, TOK / BM);
    hgemm_fc2<<<fc2_grid, 256>>>(fc2_b, out);
}

// round 13
// speedup vs baseline: 1.1029x; 1.0039x over previous
#include <cuda_runtime.h>
#include <cuda_bf16.h>
#include <stdint.h>
#include <math.h>

#define Bv    8
#define Hdim  224
#define Wdim  224
#define Cch   192
#define NHh   6
#define HD    32
#define WSz   7
#define SSz   3
#define Nwin  49
#define NWH   32
#define NWW   32
#define NWIN  1024
#define Ltok  (Hdim*Wdim)
#define TOK   (Bv*Ltok)     // 401408
#define HID   768
#define CQKV  576
#define WINTILE (Nwin*HD)   // 1568 elems per (win,sel,head) tile

typedef __nv_bfloat16 bf16;

// ---------------- scratch (device globals) ------------------------------------
__device__ bf16 g_xw[(size_t)TOK * Cch];
__device__ bf16 g_qkv[(size_t)TOK * CQKV];   // head-major: [win][sel][head][n][d]
__device__ bf16 g_att[(size_t)TOK * Cch];
__device__ bf16 g_hid[(size_t)TOK * HID];
__device__ bf16 g_wqkv[Cch * CQKV];
__device__ bf16 g_wproj[Cch * Cch];
__device__ bf16 g_wfc1[Cch * HID];
__device__ bf16 g_wfc2[HID * Cch];
__device__ bf16 g_bias[4 * NHh * 64 * 64];   // fused rpb+mask+pad table

#define NQKV  (Cch*CQKV)
#define NPROJ (Cch*Cch)
#define NFC1  (Cch*HID)
#define NFC2  (HID*Cch)
#define NCVT  (NQKV+NPROJ+NFC1+NFC2)
#define NBIAS (4*NHh*64*64)

// ---------------- fused weight fp32 -> bf16 -----------------------------------
__global__ void cvt_all_kernel(const float* __restrict__ qkv_w,
                               const float* __restrict__ proj_w,
                               const float* __restrict__ fc1_w,
                               const float* __restrict__ fc2_w)
{
    int i = blockIdx.x * 256 + threadIdx.x;
    if (i >= NCVT) return;
    if (i < NQKV) {
        g_wqkv[i] = __float2bfloat16(qkv_w[i]);
    } else if (i < NQKV + NPROJ) {
        int j = i - NQKV;
        g_wproj[j] = __float2bfloat16(proj_w[j]);
    } else if (i < NQKV + NPROJ + NFC1) {
        int j = i - NQKV - NPROJ;
        g_wfc1[j] = __float2bfloat16(fc1_w[j]);
    } else {
        int j = i - NQKV - NPROJ - NFC1;
        g_wfc2[j] = __float2bfloat16(fc2_w[j]);
    }
}

// ---------------- fused bias table: rpb + shift-mask + padding ------------------
// pattern: bit1 = bottom edge (wh==31), bit0 = right edge (ww==31)
__global__ void bias_kernel(const float* __restrict__ rpb_t)
{
    int idx = blockIdx.x * 256 + threadIdx.x;
    if (idx >= NBIAS) return;
    int j   = idx & 63;
    int i   = (idx >> 6) & 63;
    int h   = (idx >> 12) % NHh;
    int pat = idx / (NHh * 4096);
    float v;
    if (i >= Nwin || j >= Nwin) {
        v = -1e9f;
    } else {
        int ri = i / WSz, ci = i % WSz;
        int rj = j / WSz, cj = j % WSz;
        int ph = pat >> 1, pw = pat & 1;
        int ghi = ph ? (ri < 4 ? 1 : 2) : 0;
        int gwi = pw ? (ci < 4 ? 1 : 2) : 0;
        int ghj = ph ? (rj < 4 ? 1 : 2) : 0;
        int gwj = pw ? (cj < 4 ? 1 : 2) : 0;
        int gi = ghi * 3 + gwi;
        int gj = ghj * 3 + gwj;
        v = rpb_t[((ri - rj + 6) * 13 + (ci - cj + 6)) * NHh + h]
          + (gi != gj ? -100.f : 0.f);
    }
    g_bias[idx] = __float2bfloat16(v);
}

// ---------------- LN1 + shift + window-partition -------------------------------
__global__ void __launch_bounds__(256) ln1_window_kernel(
    const float* __restrict__ x, const float* __restrict__ g,
    const float* __restrict__ b)
{
    int warp = (blockIdx.x * blockDim.x + threadIdx.x) >> 5;
    int lane = threadIdx.x & 31;
    if (warp >= TOK) return;
    int bidx = warp / Ltok;
    int l    = warp % Ltok;
    const float* xr = x + (size_t)warp * Cch;
    float v[6];
    float s = 0.f;
    float ss = 0.f;
#pragma unroll
    for (int i = 0; i < 6; i++) {
        v[i] = xr[lane + 32 * i];
        s  += v[i];
        ss += v[i] * v[i];
    }
#pragma unroll
    for (int o = 16; o; o >>= 1) {
        s  += __shfl_xor_sync(0xffffffffu, s,  o);
        ss += __shfl_xor_sync(0xffffffffu, ss, o);
    }
    float mean = s * (1.f / Cch);
    float rstd = rsqrtf(ss * (1.f / Cch) - mean * mean + 1e-5f);

    int h = l / Wdim;
    int w = l % Wdim;
    int hs = h - SSz; if (hs < 0) hs += Hdim;
    int ws = w - SSz; if (ws < 0) ws += Wdim;
    int wh = hs / WSz;
    int r  = hs % WSz;
    int ww = ws / WSz;
    int c  = ws % WSz;
    int row = (bidx * NWIN + wh * NWW + ww) * Nwin + r * WSz + c;
    bf16* dst = g_xw + (size_t)row * Cch;
#pragma unroll
    for (int i = 0; i < 6; i++) {
        int ch = lane + 32 * i;
        dst[ch] = __float2bfloat16((v[i] - mean) * rstd * g[ch] + b[ch]);
    }
}

// ---------------- LN2 -----------------------------------------------------------
__global__ void __launch_bounds__(256) ln2_kernel(
    const float* __restrict__ x, const float* __restrict__ g,
    const float* __restrict__ b)
{
    int warp = (blockIdx.x * blockDim.x + threadIdx.x) >> 5;
    int lane = threadIdx.x & 31;
    if (warp >= TOK) return;
    const float* xr = x + (size_t)warp * Cch;
    float v[6];
    float s = 0.f;
    float ss = 0.f;
#pragma unroll
    for (int i = 0; i < 6; i++) {
        v[i] = xr[lane + 32 * i];
        s  += v[i];
        ss += v[i] * v[i];
    }
#pragma unroll
    for (int o = 16; o; o >>= 1) {
        s  += __shfl_xor_sync(0xffffffffu, s,  o);
        ss += __shfl_xor_sync(0xffffffffu, ss, o);
    }
    float mean = s * (1.f / Cch);
    float rstd = rsqrtf(ss * (1.f / Cch) - mean * mean + 1e-5f);
    bf16* dst = g_xw + (size_t)warp * Cch;
#pragma unroll
    for (int i = 0; i < 6; i++) {
        int ch = lane + 32 * i;
        dst[ch] = __float2bfloat16((v[i] - mean) * rstd * g[ch] + b[ch]);
    }
}

// ---------------- mma / ldmatrix helpers -----------------------------------------
__device__ __forceinline__ void ldsm_x4(uint32_t& r0, uint32_t& r1, uint32_t& r2,
                                        uint32_t& r3, const void* p)
{
    uint32_t a = (uint32_t)__cvta_generic_to_shared(p);
    asm volatile("ldmatrix.sync.aligned.m8n8.x4.shared.b16 {%0,%1,%2,%3},[%4];"
                 : "=r"(r0), "=r"(r1), "=r"(r2), "=r"(r3) : "r"(a));
}
__device__ __forceinline__ void ldsm_x4_t(uint32_t& r0, uint32_t& r1, uint32_t& r2,
                                          uint32_t& r3, const void* p)
{
    uint32_t a = (uint32_t)__cvta_generic_to_shared(p);
    asm volatile("ldmatrix.sync.aligned.m8n8.x4.trans.shared.b16 {%0,%1,%2,%3},[%4];"
                 : "=r"(r0), "=r"(r1), "=r"(r2), "=r"(r3) : "r"(a));
}
__device__ __forceinline__ void mma_bf16(float* c, const uint32_t* a, const uint32_t* b)
{
    asm volatile(
        "mma.sync.aligned.m16n8k16.row.col.f32.bf16.bf16.f32 "
        "{%0,%1,%2,%3},{%4,%5,%6,%7},{%8,%9},{%0,%1,%2,%3};"
        : "+f"(c[0]), "+f"(c[1]), "+f"(c[2]), "+f"(c[3])
        : "r"(a[0]), "r"(a[1]), "r"(a[2]), "r"(a[3]), "r"(b[0]), "r"(b[1]));
}
__device__ __forceinline__ void cp16(void* smem, const void* gmem)
{
    uint32_t a = (uint32_t)__cvta_generic_to_shared(smem);
    asm volatile("cp.async.cg.shared.global [%0], [%1], 16;" :: "r"(a), "l"(gmem));
}
__device__ __forceinline__ void cp_commit()
{
    asm volatile("cp.async.commit_group;" ::: "memory");
}
__device__ __forceinline__ void cp_wait_all()
{
    asm volatile("cp.async.wait_group 0;" ::: "memory");
}

// ---------------- bf16 tensor-core GEMM (BM=256, 8 warps x 32x64 strip) -----------
#define BM 256
#define BN 64
#define BK 32
#define ASTRIDE 40
#define BSTRIDE 72

// MODE 0: bf16 store scattered to head-major qkv layout (q pre-scaled)
// MODE 1: fp32 store, window-reverse + unshift + residual -> d_out
// MODE 2: exact GELU -> bf16 store (hidden)
// MODE 3: fp32 += (fc2 residual into d_out)
template <int MODE>
__device__ __forceinline__ void hgemm_body(
    const bf16* A, const bf16* Bw, const float* bias, void* Cout,
    int Kd, int Nd, const float* resid)
{
    __shared__ bf16 As[2][BM][ASTRIDE];
    __shared__ bf16 Bs[2][BK][BSTRIDE];

    int tid  = threadIdx.x;
    int warp = tid >> 5;
    int lane = tid & 31;
    int row0 = blockIdx.y * BM;
    int col0 = blockIdx.x * BN;

    float acc[2][8][4];
#pragma unroll
    for (int i = 0; i < 2; i++)
#pragma unroll
        for (int j = 0; j < 8; j++)
#pragma unroll
            for (int k = 0; k < 4; k++) acc[i][j][k] = 0.f;

    int ra0 = tid >> 2;
    int ka0 = (tid & 3) * 8;
    int rb = tid >> 3;
    int kb = (tid & 7) * 8;

    const bf16* Ag0 = A + (size_t)(row0 + ra0) * Kd + ka0;
    const bf16* Ag1 = Ag0 + (size_t)64 * Kd;
    const bf16* Ag2 = Ag0 + (size_t)128 * Kd;
    const bf16* Ag3 = Ag0 + (size_t)192 * Kd;
    const bf16* Bg  = Bw + (size_t)rb * Nd + col0 + kb;

    cp16(&As[0][ra0][ka0],       Ag0);
    cp16(&As[0][ra0 + 64][ka0],  Ag1);
    cp16(&As[0][ra0 + 128][ka0], Ag2);
    cp16(&As[0][ra0 + 192][ka0], Ag3);
    cp16(&Bs[0][rb][kb],         Bg);
    cp_commit();

    int buf = 0;
    for (int k0 = 0; k0 < Kd; k0 += BK) {
        cp_wait_all();
        __syncthreads();
        if (k0 + BK < Kd) {
            int nb = buf ^ 1;
            cp16(&As[nb][ra0][ka0],       Ag0 + k0 + BK);
            cp16(&As[nb][ra0 + 64][ka0],  Ag1 + k0 + BK);
            cp16(&As[nb][ra0 + 128][ka0], Ag2 + k0 + BK);
            cp16(&As[nb][ra0 + 192][ka0], Ag3 + k0 + BK);
            cp16(&Bs[nb][rb][kb],         Bg + (size_t)(k0 + BK) * Nd);
            cp_commit();
        }

#pragma unroll
        for (int ks = 0; ks < 2; ks++) {
            uint32_t af[2][4];
            uint32_t bfr[8][2];
#pragma unroll
            for (int mt = 0; mt < 2; mt++)
                ldsm_x4(af[mt][0], af[mt][1], af[mt][2], af[mt][3],
                        &As[buf][warp * 32 + mt * 16 + (lane & 15)][ks * 16 + (lane >> 4) * 8]);
#pragma unroll
            for (int bt = 0; bt < 4; bt++) {
                uint32_t r0, r1, r2, r3;
                ldsm_x4_t(r0, r1, r2, r3,
                          &Bs[buf][ks * 16 + (lane & 15)][bt * 16 + (lane >> 4) * 8]);
                bfr[bt * 2][0] = r0;
                bfr[bt * 2][1] = r1;
                bfr[bt * 2 + 1][0] = r2;
                bfr[bt * 2 + 1][1] = r3;
            }
#pragma unroll
            for (int mt = 0; mt < 2; mt++)
#pragma unroll
                for (int nt = 0; nt < 8; nt++)
                    mma_bf16(acc[mt][nt], af[mt], bfr[nt]);
        }
        buf ^= 1;
    }

#pragma unroll
    for (int mt = 0; mt < 2; mt++) {
#pragma unroll
        for (int rh = 0; rh < 2; rh++) {
            int row = row0 + warp * 32 + mt * 16 + rh * 8 + (lane >> 2);
            size_t dstrow = 0;
            int winq = 0;
            int nq = 0;
            if (MODE == 1) {
                int win = row / Nwin;
                int n = row % Nwin;
                int bb = win / NWIN;
                int w_ = win % NWIN;
                int wh = w_ / NWW;
                int ww = w_ % NWW;
                int h = wh * WSz + n / WSz + SSz; if (h >= Hdim) h -= Hdim;
                int w = ww * WSz + n % WSz + SSz; if (w >= Wdim) w -= Wdim;
                dstrow = ((size_t)bb * Ltok + h * Wdim + w) * Cch;
            } else if (MODE == 0) {
                winq = row / Nwin;
                nq   = row % Nwin;
            } else {
                dstrow = (size_t)row * Nd;
            }
#pragma unroll
            for (int nt = 0; nt < 8; nt++) {
                int col = col0 + nt * 8 + (lane & 3) * 2;
                float v0 = acc[mt][nt][rh * 2 + 0] + bias[col];
                float v1 = acc[mt][nt][rh * 2 + 1] + bias[col + 1];
                if (MODE == 0) {
                    int sel = col / Cch;
                    int hd2 = (col % Cch) >> 5;
                    int d   = col & 31;
                    if (sel == 0) {
                        v0 *= 0.1767766952966369f;
                        v1 *= 0.1767766952966369f;
                    }
                    size_t off = (((size_t)winq * 3 + sel) * NHh + hd2) * WINTILE
                               + nq * HD + d;
                    *(__nv_bfloat162*)((bf16*)Cout + off) =
                        __halves2bfloat162(__float2bfloat16(v0), __float2bfloat16(v1));
                } else if (MODE == 2) {
                    float g0 = 0.5f * v0 * (1.f + erff(v0 * 0.7071067811865475f));
                    float g1 = 0.5f * v1 * (1.f + erff(v1 * 0.7071067811865475f));
                    *(__nv_bfloat162*)((bf16*)Cout + dstrow + col) =
                        __halves2bfloat162(__float2bfloat16(g0), __float2bfloat16(g1));
                } else if (MODE == 1) {
                    float* o = (float*)Cout + dstrow + col;
                    o[0] = resid[dstrow + col]     + v0;
                    o[1] = resid[dstrow + col + 1] + v1;
                } else {
                    float* o = (float*)Cout + dstrow + col;
                    o[0] += v0;
                    o[1] += v1;
                }
            }
        }
    }
}

// ---------------- concrete GEMM wrappers ------------------------------------------
__global__ void __launch_bounds__(256, 2) hgemm_qkv(const float* __restrict__ bias)
{
    hgemm_body<0>(g_xw, g_wqkv, bias, g_qkv, Cch, CQKV, (const float*)0);
}
__global__ void __launch_bounds__(256, 2) hgemm_proj(const float* __restrict__ bias,
                                                     float* __restrict__ out,
                                                     const float* __restrict__ resid)
{
    hgemm_body<1>(g_att, g_wproj, bias, out, Cch, Cch, resid);
}
__global__ void __launch_bounds__(256, 2) hgemm_fc1(const float* __restrict__ bias)
{
    hgemm_body<2>(g_xw, g_wfc1, bias, g_hid, Cch, HID, (const float*)0);
}
__global__ void __launch_bounds__(256, 2) hgemm_fc2(const float* __restrict__ bias,
                                                    float* __restrict__ out)
{
    hgemm_body<3>(g_hid, g_wfc2, bias, out, HID, Cch, (const float*)0);
}

// ---------------- windowed attention: 2 heads/block, fused bias table --------------
__global__ void __launch_bounds__(256) attn_kernel()
{
    __shared__ bf16  qk[2][2][64][40];   // [head][0=q,1=k][row][col]; ps aliases this
    __shared__ bf16  vs[2][64][40];

    int tid  = threadIdx.x;
    int warp = tid >> 5;
    int lane = tid & 31;
    int hh   = warp >> 2;
    int wg   = warp & 3;
    int m0   = wg * 16;

    int blk  = blockIdx.x;
    int hb   = blk % 3;
    int win  = blk / 3;
    int wwin = win % NWIN;
    int pat  = ((wwin / NWW == NWH - 1) ? 2 : 0) + ((wwin % NWW == NWW - 1) ? 1 : 0);

    {
        int t   = tid & 127;
        int lh  = tid >> 7;
        int head = 2 * hb + lh;
        const bf16* bq = g_qkv + (((size_t)win * 3 + 0) * NHh + head) * WINTILE;
        const bf16* bk = g_qkv + (((size_t)win * 3 + 1) * NHh + head) * WINTILE;
        const bf16* bv = g_qkv + (((size_t)win * 3 + 2) * NHh + head) * WINTILE;
        for (int idx = t; idx < 196; idx += 128) {
            int row = idx >> 2;
            int c   = (idx & 3) * 8;
            *(uint4*)&qk[lh][0][row][c] = *(const uint4*)(bq + idx * 8);
            *(uint4*)&qk[lh][1][row][c] = *(const uint4*)(bk + idx * 8);
            *(uint4*)&vs[lh][row][c]    = *(const uint4*)(bv + idx * 8);
        }
        for (int idx = t; idx < 150; idx += 128) {
            int r  = 49 + idx / 10;
            int c4 = (idx % 10) * 4;
            uint2 z = make_uint2(0u, 0u);
            *(uint2*)&qk[lh][0][r][c4] = z;
            *(uint2*)&qk[lh][1][r][c4] = z;
            *(uint2*)&vs[lh][r][c4]    = z;
        }
    }
    __syncthreads();

    float c[8][4];
#pragma unroll
    for (int nt = 0; nt < 8; nt++)
#pragma unroll
        for (int e = 0; e < 4; e++) c[nt][e] = 0.f;
    {
        uint32_t a[2][4];
#pragma unroll
        for (int ksx = 0; ksx < 2; ksx++)
            ldsm_x4(a[ksx][0], a[ksx][1], a[ksx][2], a[ksx][3],
                    &qk[hh][0][m0 + (lane & 15)][ksx * 16 + (lane >> 4) * 8]);
#pragma unroll
        for (int jt = 0; jt < 4; jt++) {
#pragma unroll
            for (int ksx = 0; ksx < 2; ksx++) {
                uint32_t r0, r1, r2, r3;
                ldsm_x4(r0, r1, r2, r3,
                        &qk[hh][1][jt * 16 + (lane & 15)][ksx * 16 + (lane >> 4) * 8]);
                uint32_t b0[2];
                uint32_t b1[2];
                b0[0] = r0; b0[1] = r2;
                b1[0] = r1; b1[1] = r3;
                mma_bf16(c[jt * 2],     a[ksx], b0);
                mma_bf16(c[jt * 2 + 1], a[ksx], b1);
            }
        }
    }
    __syncthreads();

    bf16* psp = &qk[hh][0][0][0];

    {
        int head = 2 * hb + hh;
        int i0 = m0 + (lane >> 2);
        int i1 = i0 + 8;
        int j0 = (lane & 3) * 2;
        const bf16* brow = g_bias + ((size_t)pat * NHh + head) * 4096;

        // add fused bias (rpb + mask + padding kill) straight from L2
#pragma unroll
        for (int nt = 0; nt < 8; nt++) {
            __nv_bfloat162 b0 = *(const __nv_bfloat162*)(brow + i0 * 64 + nt * 8 + j0);
            __nv_bfloat162 b1 = *(const __nv_bfloat162*)(brow + i1 * 64 + nt * 8 + j0);
            float2 f0 = __bfloat1622float2(b0);
            float2 f1 = __bfloat1622float2(b1);
            c[nt][0] += f0.x;
            c[nt][1] += f0.y;
            c[nt][2] += f1.x;
            c[nt][3] += f1.y;
        }

        float mx0 = -1e30f;
        float mx1 = -1e30f;
#pragma unroll
        for (int nt = 0; nt < 8; nt++) {
            mx0 = fmaxf(mx0, fmaxf(c[nt][0], c[nt][1]));
            mx1 = fmaxf(mx1, fmaxf(c[nt][2], c[nt][3]));
        }
        mx0 = fmaxf(mx0, __shfl_xor_sync(0xffffffffu, mx0, 1));
        mx0 = fmaxf(mx0, __shfl_xor_sync(0xffffffffu, mx0, 2));
        mx1 = fmaxf(mx1, __shfl_xor_sync(0xffffffffu, mx1, 1));
        mx1 = fmaxf(mx1, __shfl_xor_sync(0xffffffffu, mx1, 2));

        float sm0 = 0.f;
        float sm1 = 0.f;
#pragma unroll
        for (int nt = 0; nt < 8; nt++) {
            c[nt][0] = __expf(c[nt][0] - mx0);
            c[nt][1] = __expf(c[nt][1] - mx0);
            c[nt][2] = __expf(c[nt][2] - mx1);
            c[nt][3] = __expf(c[nt][3] - mx1);
            sm0 += c[nt][0] + c[nt][1];
            sm1 += c[nt][2] + c[nt][3];
        }
        sm0 += __shfl_xor_sync(0xffffffffu, sm0, 1);
        sm0 += __shfl_xor_sync(0xffffffffu, sm0, 2);
        sm1 += __shfl_xor_sync(0xffffffffu, sm1, 1);
        sm1 += __shfl_xor_sync(0xffffffffu, sm1, 2);
        float inv0 = 1.f / sm0;
        float inv1 = 1.f / sm1;

#pragma unroll
        for (int nt = 0; nt < 8; nt++) {
            *(__nv_bfloat162*)&psp[i0 * 72 + nt * 8 + j0] =
                __halves2bfloat162(__float2bfloat16(c[nt][0] * inv0),
                                   __float2bfloat16(c[nt][1] * inv0));
            *(__nv_bfloat162*)&psp[i1 * 72 + nt * 8 + j0] =
                __halves2bfloat162(__float2bfloat16(c[nt][2] * inv1),
                                   __float2bfloat16(c[nt][3] * inv1));
        }
    }
    __syncthreads();

    {
        float o[4][4];
#pragma unroll
        for (int nt = 0; nt < 4; nt++)
#pragma unroll
            for (int e = 0; e < 4; e++) o[nt][e] = 0.f;

#pragma unroll
        for (int ksx = 0; ksx < 4; ksx++) {
            uint32_t a[4];
            ldsm_x4(a[0], a[1], a[2], a[3],
                    &psp[(m0 + (lane & 15)) * 72 + ksx * 16 + (lane >> 4) * 8]);
#pragma unroll
            for (int bt = 0; bt < 2; bt++) {
                uint32_t r0, r1, r2, r3;
                ldsm_x4_t(r0, r1, r2, r3,
                          &vs[hh][ksx * 16 + (lane & 15)][bt * 16 + (lane >> 4) * 8]);
                uint32_t b0[2];
                uint32_t b1[2];
                b0[0] = r0; b0[1] = r1;
                b1[0] = r2; b1[1] = r3;
                mma_bf16(o[bt * 2],     a, b0);
                mma_bf16(o[bt * 2 + 1], a, b1);
            }
        }

        bf16* outw = g_att + (size_t)win * Nwin * Cch + (2 * hb + hh) * HD;
        int i0 = m0 + (lane >> 2);
#pragma unroll
        for (int nt = 0; nt < 4; nt++) {
            int d = nt * 8 + (lane & 3) * 2;
            if (i0 < Nwin) {
                *(__nv_bfloat162*)(outw + (size_t)i0 * Cch + d) =
                    __halves2bfloat162(__float2bfloat16(o[nt][0]), __float2bfloat16(o[nt][1]));
            }
            if (i0 + 8 < Nwin) {
                *(__nv_bfloat162*)(outw + (size_t)(i0 + 8) * Cch + d) =
                    __halves2bfloat162(__float2bfloat16(o[nt][2]), __float2bfloat16(o[nt][3]));
            }
        }
    }
}

// ---------------- launch ----------------------------------------------------------
extern "C" void kernel_launch(void* const* d_in, const int* in_sizes, int n_in,
                              void* d_out, int out_size)
{
    const float* x       = (const float*)d_in[0];
    const float* norm1_g = (const float*)d_in[1];
    const float* norm1_b = (const float*)d_in[2];
    const float* qkv_w   = (const float*)d_in[3];
    const float* qkv_b   = (const float*)d_in[4];
    const float* rpb_t   = (const float*)d_in[5];
    const float* proj_w  = (const float*)d_in[6];
    const float* proj_b  = (const float*)d_in[7];
    const float* norm2_g = (const float*)d_in[8];
    const float* norm2_b = (const float*)d_in[9];
    const float* fc1_w   = (const float*)d_in[10];
    const float* fc1_b   = (const float*)d_in[11];
    const float* fc2_w   = (const float*)d_in[12];
    const float* fc2_b   = (const float*)d_in[13];
    float* out = (float*)d_out;

    dim3 cvt_grid((NCVT + 255) / 256);
    cvt_all_kernel<<<cvt_grid, 256>>>(qkv_w, proj_w, fc1_w, fc2_w);

    dim3 bias_grid((NBIAS + 255) / 256);
    bias_kernel<<<bias_grid, 256>>>(rpb_t);

    dim3 ln_grid(TOK / 8);
    ln1_window_kernel<<<ln_grid, 256>>>(x, norm1_g, norm1_b);

    dim3 qkv_grid(CQKV / BN, TOK / BM);
    hgemm_qkv<<<qkv_grid, 256>>>(qkv_b);

    dim3 attn_grid((TOK / Nwin) * 3);
    attn_kernel<<<attn_grid, 256>>>();

    dim3 proj_grid(Cch / BN, TOK / BM);
    hgemm_proj<<<proj_grid, 256>>>(proj_b, out, x);

    ln2_kernel<<<ln_grid, 256>>>(out, norm2_g, norm2_b);

    dim3 fc1_grid(HID / BN, TOK / BM);
    hgemm_fc1<<<fc1_grid, 256>>>(fc1_b);

    dim3 fc2_grid(Cch / BN, TOK / BM);
    hgemm_fc2<<<fc2_grid, 256>>>(fc2_b, out);
}

// round 14
// speedup vs baseline: 1.1219x; 1.0172x over previous
#include <cuda_runtime.h>
#include <cuda_bf16.h>
#include <stdint.h>
#include <math.h>

#define Bv    8
#define Hdim  224
#define Wdim  224
#define Cch   192
#define NHh   6
#define HD    32
#define WSz   7
#define SSz   3
#define Nwin  49
#define NWH   32
#define NWW   32
#define NWIN  1024
#define Ltok  (Hdim*Wdim)
#define TOK   (Bv*Ltok)     // 401408
#define HID   768
#define CQKV  576
#define WINTILE (Nwin*HD)

typedef __nv_bfloat16 bf16;

// ---------------- scratch (device globals) ------------------------------------
__device__ bf16 g_xw[(size_t)TOK * Cch];
__device__ bf16 g_qkv[(size_t)TOK * CQKV];   // head-major: [win][sel][head][n][d]
__device__ bf16 g_att[(size_t)TOK * Cch];
__device__ bf16 g_hid[(size_t)TOK * HID];
__device__ bf16 g_wqkv[Cch * CQKV];
__device__ bf16 g_wproj[Cch * Cch];
__device__ bf16 g_wfc1[Cch * HID];
__device__ bf16 g_wfc2[HID * Cch];
__device__ bf16 g_bias[4 * NHh * 64 * 64];

#define NQKV  (Cch*CQKV)
#define NPROJ (Cch*Cch)
#define NFC1  (Cch*HID)
#define NFC2  (HID*Cch)
#define NCVT  (NQKV+NPROJ+NFC1+NFC2)
#define NBIAS (4*NHh*64*64)

// ---------------- fused weight fp32 -> bf16 -----------------------------------
__global__ void cvt_all_kernel(const float* __restrict__ qkv_w,
                               const float* __restrict__ proj_w,
                               const float* __restrict__ fc1_w,
                               const float* __restrict__ fc2_w)
{
    int i = blockIdx.x * 256 + threadIdx.x;
    if (i >= NCVT) return;
    if (i < NQKV) {
        g_wqkv[i] = __float2bfloat16(qkv_w[i]);
    } else if (i < NQKV + NPROJ) {
        int j = i - NQKV;
        g_wproj[j] = __float2bfloat16(proj_w[j]);
    } else if (i < NQKV + NPROJ + NFC1) {
        int j = i - NQKV - NPROJ;
        g_wfc1[j] = __float2bfloat16(fc1_w[j]);
    } else {
        int j = i - NQKV - NPROJ - NFC1;
        g_wfc2[j] = __float2bfloat16(fc2_w[j]);
    }
}

// ---------------- fused bias table: rpb + shift-mask + padding ------------------
__global__ void bias_kernel(const float* __restrict__ rpb_t)
{
    int idx = blockIdx.x * 256 + threadIdx.x;
    if (idx >= NBIAS) return;
    int j   = idx & 63;
    int i   = (idx >> 6) & 63;
    int h   = (idx >> 12) % NHh;
    int pat = idx / (NHh * 4096);
    float v;
    if (i >= Nwin || j >= Nwin) {
        v = -1e9f;
    } else {
        int ri = i / WSz, ci = i % WSz;
        int rj = j / WSz, cj = j % WSz;
        int ph = pat >> 1, pw = pat & 1;
        int ghi = ph ? (ri < 4 ? 1 : 2) : 0;
        int gwi = pw ? (ci < 4 ? 1 : 2) : 0;
        int ghj = ph ? (rj < 4 ? 1 : 2) : 0;
        int gwj = pw ? (cj < 4 ? 1 : 2) : 0;
        int gi = ghi * 3 + gwi;
        int gj = ghj * 3 + gwj;
        v = rpb_t[((ri - rj + 6) * 13 + (ci - cj + 6)) * NHh + h]
          + (gi != gj ? -100.f : 0.f);
    }
    g_bias[idx] = __float2bfloat16(v);
}

// ---------------- LN1 + shift + window-partition -------------------------------
__global__ void __launch_bounds__(256) ln1_window_kernel(
    const float* __restrict__ x, const float* __restrict__ g,
    const float* __restrict__ b)
{
    int warp = (blockIdx.x * blockDim.x + threadIdx.x) >> 5;
    int lane = threadIdx.x & 31;
    if (warp >= TOK) return;
    int bidx = warp / Ltok;
    int l    = warp % Ltok;
    const float* xr = x + (size_t)warp * Cch;
    float v[6];
    float s = 0.f;
    float ss = 0.f;
#pragma unroll
    for (int i = 0; i < 6; i++) {
        v[i] = xr[lane + 32 * i];
        s  += v[i];
        ss += v[i] * v[i];
    }
#pragma unroll
    for (int o = 16; o; o >>= 1) {
        s  += __shfl_xor_sync(0xffffffffu, s,  o);
        ss += __shfl_xor_sync(0xffffffffu, ss, o);
    }
    float mean = s * (1.f / Cch);
    float rstd = rsqrtf(ss * (1.f / Cch) - mean * mean + 1e-5f);

    int h = l / Wdim;
    int w = l % Wdim;
    int hs = h - SSz; if (hs < 0) hs += Hdim;
    int ws = w - SSz; if (ws < 0) ws += Wdim;
    int wh = hs / WSz;
    int r  = hs % WSz;
    int ww = ws / WSz;
    int c  = ws % WSz;
    int row = (bidx * NWIN + wh * NWW + ww) * Nwin + r * WSz + c;
    bf16* dst = g_xw + (size_t)row * Cch;
#pragma unroll
    for (int i = 0; i < 6; i++) {
        int ch = lane + 32 * i;
        dst[ch] = __float2bfloat16((v[i] - mean) * rstd * g[ch] + b[ch]);
    }
}

// ---------------- LN2 -----------------------------------------------------------
__global__ void __launch_bounds__(256) ln2_kernel(
    const float* __restrict__ x, const float* __restrict__ g,
    const float* __restrict__ b)
{
    int warp = (blockIdx.x * blockDim.x + threadIdx.x) >> 5;
    int lane = threadIdx.x & 31;
    if (warp >= TOK) return;
    const float* xr = x + (size_t)warp * Cch;
    float v[6];
    float s = 0.f;
    float ss = 0.f;
#pragma unroll
    for (int i = 0; i < 6; i++) {
        v[i] = xr[lane + 32 * i];
        s  += v[i];
        ss += v[i] * v[i];
    }
#pragma unroll
    for (int o = 16; o; o >>= 1) {
        s  += __shfl_xor_sync(0xffffffffu, s,  o);
        ss += __shfl_xor_sync(0xffffffffu, ss, o);
    }
    float mean = s * (1.f / Cch);
    float rstd = rsqrtf(ss * (1.f / Cch) - mean * mean + 1e-5f);
    bf16* dst = g_xw + (size_t)warp * Cch;
#pragma unroll
    for (int i = 0; i < 6; i++) {
        int ch = lane + 32 * i;
        dst[ch] = __float2bfloat16((v[i] - mean) * rstd * g[ch] + b[ch]);
    }
}

// ---------------- mma / ldmatrix helpers -----------------------------------------
__device__ __forceinline__ void ldsm_x4(uint32_t& r0, uint32_t& r1, uint32_t& r2,
                                        uint32_t& r3, const void* p)
{
    uint32_t a = (uint32_t)__cvta_generic_to_shared(p);
    asm volatile("ldmatrix.sync.aligned.m8n8.x4.shared.b16 {%0,%1,%2,%3},[%4];"
                 : "=r"(r0), "=r"(r1), "=r"(r2), "=r"(r3) : "r"(a));
}
__device__ __forceinline__ void ldsm_x4_t(uint32_t& r0, uint32_t& r1, uint32_t& r2,
                                          uint32_t& r3, const void* p)
{
    uint32_t a = (uint32_t)__cvta_generic_to_shared(p);
    asm volatile("ldmatrix.sync.aligned.m8n8.x4.trans.shared.b16 {%0,%1,%2,%3},[%4];"
                 : "=r"(r0), "=r"(r1), "=r"(r2), "=r"(r3) : "r"(a));
}
__device__ __forceinline__ void mma_bf16(float* c, const uint32_t* a, const uint32_t* b)
{
    asm volatile(
        "mma.sync.aligned.m16n8k16.row.col.f32.bf16.bf16.f32 "
        "{%0,%1,%2,%3},{%4,%5,%6,%7},{%8,%9},{%0,%1,%2,%3};"
        : "+f"(c[0]), "+f"(c[1]), "+f"(c[2]), "+f"(c[3])
        : "r"(a[0]), "r"(a[1]), "r"(a[2]), "r"(a[3]), "r"(b[0]), "r"(b[1]));
}
__device__ __forceinline__ void cp16(void* smem, const void* gmem)
{
    uint32_t a = (uint32_t)__cvta_generic_to_shared(smem);
    asm volatile("cp.async.cg.shared.global [%0], [%1], 16;" :: "r"(a), "l"(gmem));
}
__device__ __forceinline__ void cp_commit()
{
    asm volatile("cp.async.commit_group;" ::: "memory");
}
__device__ __forceinline__ void cp_wait1()
{
    asm volatile("cp.async.wait_group 1;" ::: "memory");
}

// ---------------- bf16 tensor-core GEMM (BM=128, 3-stage cp.async ring) -----------
#define BM 128
#define BN 64
#define BK 32
#define ASTRIDE 40
#define BSTRIDE 72

// MODE 0: bf16 store scattered to head-major qkv layout (q pre-scaled)
// MODE 1: fp32 store, window-reverse + unshift + residual -> d_out
// MODE 2: exact GELU -> bf16 store (hidden)
// MODE 3: fp32 += (fc2 residual into d_out)
template <int MODE>
__device__ __forceinline__ void hgemm_body(
    const bf16* A, const bf16* Bw, const float* bias, void* Cout,
    int Kd, int Nd, const float* resid)
{
    __shared__ bf16 As[3][BM][ASTRIDE];
    __shared__ bf16 Bs[3][BK][BSTRIDE];

    int tid  = threadIdx.x;
    int warp = tid >> 5;
    int lane = tid & 31;
    int wm = warp >> 1;
    int wn = warp & 1;
    int row0 = blockIdx.y * BM;
    int col0 = blockIdx.x * BN;

    float acc[2][4][4];
#pragma unroll
    for (int i = 0; i < 2; i++)
#pragma unroll
        for (int j = 0; j < 4; j++)
#pragma unroll
            for (int k = 0; k < 4; k++) acc[i][j][k] = 0.f;

    int ra0 = tid >> 2;
    int ka0 = (tid & 3) * 8;
    int ra1 = ra0 + 64;
    int rb = tid >> 3;
    int kb = (tid & 7) * 8;

    const bf16* Ag0 = A + (size_t)(row0 + ra0) * Kd + ka0;
    const bf16* Ag1 = A + (size_t)(row0 + ra1) * Kd + ka0;
    const bf16* Bg  = Bw + (size_t)rb * Nd + col0 + kb;

    int nit = Kd / BK;

    // prologue: stages 0 and 1
    cp16(&As[0][ra0][ka0], Ag0);
    cp16(&As[0][ra1][ka0], Ag1);
    cp16(&Bs[0][rb][kb],   Bg);
    cp_commit();
    if (nit > 1) {
        cp16(&As[1][ra0][ka0], Ag0 + BK);
        cp16(&As[1][ra1][ka0], Ag1 + BK);
        cp16(&Bs[1][rb][kb],   Bg + (size_t)BK * Nd);
    }
    cp_commit();

    int buf = 0;
    int ld  = 2;
    for (int it = 0; it < nit; it++) {
        cp_wait1();
        __syncthreads();
        if (it + 2 < nit) {
            int k2 = (it + 2) * BK;
            cp16(&As[ld][ra0][ka0], Ag0 + k2);
            cp16(&As[ld][ra1][ka0], Ag1 + k2);
            cp16(&Bs[ld][rb][kb],   Bg + (size_t)k2 * Nd);
            cp_commit();
            ld = (ld == 2) ? 0 : ld + 1;
        } else {
            cp_commit();   // keep group count consistent for wait_group 1
        }

#pragma unroll
        for (int ks = 0; ks < 2; ks++) {
            uint32_t af[2][4];
            uint32_t bfr[4][2];
#pragma unroll
            for (int mt = 0; mt < 2; mt++)
                ldsm_x4(af[mt][0], af[mt][1], af[mt][2], af[mt][3],
                        &As[buf][wm * 32 + mt * 16 + (lane & 15)][ks * 16 + (lane >> 4) * 8]);
#pragma unroll
            for (int bt = 0; bt < 2; bt++) {
                uint32_t r0, r1, r2, r3;
                ldsm_x4_t(r0, r1, r2, r3,
                          &Bs[buf][ks * 16 + (lane & 15)][wn * 32 + bt * 16 + (lane >> 4) * 8]);
                bfr[bt * 2][0] = r0;
                bfr[bt * 2][1] = r1;
                bfr[bt * 2 + 1][0] = r2;
                bfr[bt * 2 + 1][1] = r3;
            }
#pragma unroll
            for (int mt = 0; mt < 2; mt++)
#pragma unroll
                for (int nt = 0; nt < 4; nt++)
                    mma_bf16(acc[mt][nt], af[mt], bfr[nt]);
        }
        buf = (buf == 2) ? 0 : buf + 1;
    }

#pragma unroll
    for (int mt = 0; mt < 2; mt++) {
#pragma unroll
        for (int rh = 0; rh < 2; rh++) {
            int row = row0 + wm * 32 + mt * 16 + rh * 8 + (lane >> 2);
            size_t dstrow = 0;
            int winq = 0;
            int nq = 0;
            if (MODE == 1) {
                int win = row / Nwin;
                int n = row % Nwin;
                int bb = win / NWIN;
                int w_ = win % NWIN;
                int wh = w_ / NWW;
                int ww = w_ % NWW;
                int h = wh * WSz + n / WSz + SSz; if (h >= Hdim) h -= Hdim;
                int w = ww * WSz + n % WSz + SSz; if (w >= Wdim) w -= Wdim;
                dstrow = ((size_t)bb * Ltok + h * Wdim + w) * Cch;
            } else if (MODE == 0) {
                winq = row / Nwin;
                nq   = row % Nwin;
            } else {
                dstrow = (size_t)row * Nd;
            }
#pragma unroll
            for (int nt = 0; nt < 4; nt++) {
                int col = col0 + wn * 32 + nt * 8 + (lane & 3) * 2;
                float v0 = acc[mt][nt][rh * 2 + 0] + bias[col];
                float v1 = acc[mt][nt][rh * 2 + 1] + bias[col + 1];
                if (MODE == 0) {
                    int sel = col / Cch;
                    int hd2 = (col % Cch) >> 5;
                    int d   = col & 31;
                    if (sel == 0) {
                        v0 *= 0.1767766952966369f;
                        v1 *= 0.1767766952966369f;
                    }
                    size_t off = (((size_t)winq * 3 + sel) * NHh + hd2) * WINTILE
                               + nq * HD + d;
                    *(__nv_bfloat162*)((bf16*)Cout + off) =
                        __halves2bfloat162(__float2bfloat16(v0), __float2bfloat16(v1));
                } else if (MODE == 2) {
                    float g0 = 0.5f * v0 * (1.f + erff(v0 * 0.7071067811865475f));
                    float g1 = 0.5f * v1 * (1.f + erff(v1 * 0.7071067811865475f));
                    *(__nv_bfloat162*)((bf16*)Cout + dstrow + col) =
                        __halves2bfloat162(__float2bfloat16(g0), __float2bfloat16(g1));
                } else if (MODE == 1) {
                    float* o = (float*)Cout + dstrow + col;
                    o[0] = resid[dstrow + col]     + v0;
                    o[1] = resid[dstrow + col + 1] + v1;
                } else {
                    float* o = (float*)Cout + dstrow + col;
                    o[0] += v0;
                    o[1] += v1;
                }
            }
        }
    }
}

// ---------------- concrete GEMM wrappers ------------------------------------------
__global__ void __launch_bounds__(256) hgemm_qkv(const float* __restrict__ bias)
{
    hgemm_body<0>(g_xw, g_wqkv, bias, g_qkv, Cch, CQKV, (const float*)0);
}
__global__ void __launch_bounds__(256) hgemm_proj(const float* __restrict__ bias,
                                                  float* __restrict__ out,
                                                  const float* __restrict__ resid)
{
    hgemm_body<1>(g_att, g_wproj, bias, out, Cch, Cch, resid);
}
__global__ void __launch_bounds__(256) hgemm_fc1(const float* __restrict__ bias)
{
    hgemm_body<2>(g_xw, g_wfc1, bias, g_hid, Cch, HID, (const float*)0);
}
__global__ void __launch_bounds__(256) hgemm_fc2(const float* __restrict__ bias,
                                                 float* __restrict__ out)
{
    hgemm_body<3>(g_hid, g_wfc2, bias, out, HID, Cch, (const float*)0);
}

// ---------------- windowed attention: 2 heads/block, fused bias table --------------
__global__ void __launch_bounds__(256) attn_kernel()
{
    __shared__ bf16  qk[2][2][64][40];
    __shared__ bf16  vs[2][64][40];

    int tid  = threadIdx.x;
    int warp = tid >> 5;
    int lane = tid & 31;
    int hh   = warp >> 2;
    int wg   = warp & 3;
    int m0   = wg * 16;

    int blk  = blockIdx.x;
    int hb   = blk % 3;
    int win  = blk / 3;
    int wwin = win % NWIN;
    int pat  = ((wwin / NWW == NWH - 1) ? 2 : 0) + ((wwin % NWW == NWW - 1) ? 1 : 0);

    {
        int t   = tid & 127;
        int lh  = tid >> 7;
        int head = 2 * hb + lh;
        const bf16* bq = g_qkv + (((size_t)win * 3 + 0) * NHh + head) * WINTILE;
        const bf16* bk = g_qkv + (((size_t)win * 3 + 1) * NHh + head) * WINTILE;
        const bf16* bv = g_qkv + (((size_t)win * 3 + 2) * NHh + head) * WINTILE;
        for (int idx = t; idx < 196; idx += 128) {
            int row = idx >> 2;
            int c   = (idx & 3) * 8;
            *(uint4*)&qk[lh][0][row][c] = *(const uint4*)(bq + idx * 8);
            *(uint4*)&qk[lh][1][row][c] = *(const uint4*)(bk + idx * 8);
            *(uint4*)&vs[lh][row][c]    = *(const uint4*)(bv + idx * 8);
        }
        for (int idx = t; idx < 150; idx += 128) {
            int r  = 49 + idx / 10;
            int c4 = (idx % 10) * 4;
            uint2 z = make_uint2(0u, 0u);
            *(uint2*)&qk[lh][0][r][c4] = z;
            *(uint2*)&qk[lh][1][r][c4] = z;
            *(uint2*)&vs[lh][r][c4]    = z;
        }
    }
    __syncthreads();

    float c[8][4];
#pragma unroll
    for (int nt = 0; nt < 8; nt++)
#pragma unroll
        for (int e = 0; e < 4; e++) c[nt][e] = 0.f;
    {
        uint32_t a[2][4];
#pragma unroll
        for (int ksx = 0; ksx < 2; ksx++)
            ldsm_x4(a[ksx][0], a[ksx][1], a[ksx][2], a[ksx][3],
                    &qk[hh][0][m0 + (lane & 15)][ksx * 16 + (lane >> 4) * 8]);
#pragma unroll
        for (int jt = 0; jt < 4; jt++) {
#pragma unroll
            for (int ksx = 0; ksx < 2; ksx++) {
                uint32_t r0, r1, r2, r3;
                ldsm_x4(r0, r1, r2, r3,
                        &qk[hh][1][jt * 16 + (lane & 15)][ksx * 16 + (lane >> 4) * 8]);
                uint32_t b0[2];
                uint32_t b1[2];
                b0[0] = r0; b0[1] = r2;
                b1[0] = r1; b1[1] = r3;
                mma_bf16(c[jt * 2],     a[ksx], b0);
                mma_bf16(c[jt * 2 + 1], a[ksx], b1);
            }
        }
    }
    __syncthreads();

    bf16* psp = &qk[hh][0][0][0];

    {
        int head = 2 * hb + hh;
        int i0 = m0 + (lane >> 2);
        int i1 = i0 + 8;
        int j0 = (lane & 3) * 2;
        const bf16* brow = g_bias + ((size_t)pat * NHh + head) * 4096;

#pragma unroll
        for (int nt = 0; nt < 8; nt++) {
            __nv_bfloat162 b0 = *(const __nv_bfloat162*)(brow + i0 * 64 + nt * 8 + j0);
            __nv_bfloat162 b1 = *(const __nv_bfloat162*)(brow + i1 * 64 + nt * 8 + j0);
            float2 f0 = __bfloat1622float2(b0);
            float2 f1 = __bfloat1622float2(b1);
            c[nt][0] += f0.x;
            c[nt][1] += f0.y;
            c[nt][2] += f1.x;
            c[nt][3] += f1.y;
        }

        float mx0 = -1e30f;
        float mx1 = -1e30f;
#pragma unroll
        for (int nt = 0; nt < 8; nt++) {
            mx0 = fmaxf(mx0, fmaxf(c[nt][0], c[nt][1]));
            mx1 = fmaxf(mx1, fmaxf(c[nt][2], c[nt][3]));
        }
        mx0 = fmaxf(mx0, __shfl_xor_sync(0xffffffffu, mx0, 1));
        mx0 = fmaxf(mx0, __shfl_xor_sync(0xffffffffu, mx0, 2));
        mx1 = fmaxf(mx1, __shfl_xor_sync(0xffffffffu, mx1, 1));
        mx1 = fmaxf(mx1, __shfl_xor_sync(0xffffffffu, mx1, 2));

        float sm0 = 0.f;
        float sm1 = 0.f;
#pragma unroll
        for (int nt = 0; nt < 8; nt++) {
            c[nt][0] = __expf(c[nt][0] - mx0);
            c[nt][1] = __expf(c[nt][1] - mx0);
            c[nt][2] = __expf(c[nt][2] - mx1);
            c[nt][3] = __expf(c[nt][3] - mx1);
            sm0 += c[nt][0] + c[nt][1];
            sm1 += c[nt][2] + c[nt][3];
        }
        sm0 += __shfl_xor_sync(0xffffffffu, sm0, 1);
        sm0 += __shfl_xor_sync(0xffffffffu, sm0, 2);
        sm1 += __shfl_xor_sync(0xffffffffu, sm1, 1);
        sm1 += __shfl_xor_sync(0xffffffffu, sm1, 2);
        float inv0 = 1.f / sm0;
        float inv1 = 1.f / sm1;

#pragma unroll
        for (int nt = 0; nt < 8; nt++) {
            *(__nv_bfloat162*)&psp[i0 * 72 + nt * 8 + j0] =
                __halves2bfloat162(__float2bfloat16(c[nt][0] * inv0),
                                   __float2bfloat16(c[nt][1] * inv0));
            *(__nv_bfloat162*)&psp[i1 * 72 + nt * 8 + j0] =
                __halves2bfloat162(__float2bfloat16(c[nt][2] * inv1),
                                   __float2bfloat16(c[nt][3] * inv1));
        }
    }
    __syncthreads();

    {
        float o[4][4];
#pragma unroll
        for (int nt = 0; nt < 4; nt++)
#pragma unroll
            for (int e = 0; e < 4; e++) o[nt][e] = 0.f;

#pragma unroll
        for (int ksx = 0; ksx < 4; ksx++) {
            uint32_t a[4];
            ldsm_x4(a[0], a[1], a[2], a[3],
                    &psp[(m0 + (lane & 15)) * 72 + ksx * 16 + (lane >> 4) * 8]);
#pragma unroll
            for (int bt = 0; bt < 2; bt++) {
                uint32_t r0, r1, r2, r3;
                ldsm_x4_t(r0, r1, r2, r3,
                          &vs[hh][ksx * 16 + (lane & 15)][bt * 16 + (lane >> 4) * 8]);
                uint32_t b0[2];
                uint32_t b1[2];
                b0[0] = r0; b0[1] = r1;
                b1[0] = r2; b1[1] = r3;
                mma_bf16(o[bt * 2],     a, b0);
                mma_bf16(o[bt * 2 + 1], a, b1);
            }
        }

        bf16* outw = g_att + (size_t)win * Nwin * Cch + (2 * hb + hh) * HD;
        int i0 = m0 + (lane >> 2);
#pragma unroll
        for (int nt = 0; nt < 4; nt++) {
            int d = nt * 8 + (lane & 3) * 2;
            if (i0 < Nwin) {
                *(__nv_bfloat162*)(outw + (size_t)i0 * Cch + d) =
                    __halves2bfloat162(__float2bfloat16(o[nt][0]), __float2bfloat16(o[nt][1]));
            }
            if (i0 + 8 < Nwin) {
                *(__nv_bfloat162*)(outw + (size_t)(i0 + 8) * Cch + d) =
                    __halves2bfloat162(__float2bfloat16(o[nt][2]), __float2bfloat16(o[nt][3]));
            }
        }
    }
}

// ---------------- launch ----------------------------------------------------------
extern "C" void kernel_launch(void* const* d_in, const int* in_sizes, int n_in,
                              void* d_out, int out_size)
{
    const float* x       = (const float*)d_in[0];
    const float* norm1_g = (const float*)d_in[1];
    const float* norm1_b = (const float*)d_in[2];
    const float* qkv_w   = (const float*)d_in[3];
    const float* qkv_b   = (const float*)d_in[4];
    const float* rpb_t   = (const float*)d_in[5];
    const float* proj_w  = (const float*)d_in[6];
    const float* proj_b  = (const float*)d_in[7];
    const float* norm2_g = (const float*)d_in[8];
    const float* norm2_b = (const float*)d_in[9];
    const float* fc1_w   = (const float*)d_in[10];
    const float* fc1_b   = (const float*)d_in[11];
    const float* fc2_w   = (const float*)d_in[12];
    const float* fc2_b   = (const float*)d_in[13];
    float* out = (float*)d_out;

    dim3 cvt_grid((NCVT + 255) / 256);
    cvt_all_kernel<<<cvt_grid, 256>>>(qkv_w, proj_w, fc1_w, fc2_w);

    dim3 bias_grid((NBIAS + 255) / 256);
    bias_kernel<<<bias_grid, 256>>>(rpb_t);

    dim3 ln_grid(TOK / 8);
    ln1_window_kernel<<<ln_grid, 256>>>(x, norm1_g, norm1_b);

    dim3 qkv_grid(CQKV / BN, TOK / BM);
    hgemm_qkv<<<qkv_grid, 256>>>(qkv_b);

    dim3 attn_grid((TOK / Nwin) * 3);
    attn_kernel<<<attn_grid, 256>>>();

    dim3 proj_grid(Cch / BN, TOK / BM);
    hgemm_proj<<<proj_grid, 256>>>(proj_b, out, x);

    ln2_kernel<<<ln_grid, 256>>>(out, norm2_g, norm2_b);

    dim3 fc1_grid(HID / BN, TOK / BM);
    hgemm_fc1<<<fc1_grid, 256>>>(fc1_b);

    dim3 fc2_grid(Cch / BN, TOK / BM);
    hgemm_fc2<<<fc2_grid, 256>>>(fc2_b, out);
}

// round 15
// speedup vs baseline: 1.1292x; 1.0065x over previous
#include <cuda_runtime.h>
#include <cuda_bf16.h>
#include <stdint.h>
#include <math.h>

#define Bv    8
#define Hdim  224
#define Wdim  224
#define Cch   192
#define NHh   6
#define HD    32
#define WSz   7
#define SSz   3
#define Nwin  49
#define NWH   32
#define NWW   32
#define NWIN  1024
#define Ltok  (Hdim*Wdim)
#define TOK   (Bv*Ltok)     // 401408
#define HID   768
#define CQKV  576
#define WINTILE (Nwin*HD)

typedef __nv_bfloat16 bf16;

// ---------------- scratch (device globals) ------------------------------------
__device__ bf16 g_xw[(size_t)TOK * Cch];
__device__ bf16 g_qkv[(size_t)TOK * CQKV];   // head-major: [win][sel][head][n][d]
__device__ bf16 g_att[(size_t)TOK * Cch];
__device__ bf16 g_hid[(size_t)TOK * HID];
__device__ bf16 g_wqkv[Cch * CQKV];
__device__ bf16 g_wproj[Cch * Cch];
__device__ bf16 g_wfc1[Cch * HID];
__device__ bf16 g_wfc2[HID * Cch];
__device__ bf16 g_bias[4 * NHh * 64 * 64];

#define NQKV  (Cch*CQKV)
#define NPROJ (Cch*Cch)
#define NFC1  (Cch*HID)
#define NFC2  (HID*Cch)
#define NCVT  (NQKV+NPROJ+NFC1+NFC2)
#define NBIAS (4*NHh*64*64)

// ---------------- fused weight fp32 -> bf16 -----------------------------------
__global__ void cvt_all_kernel(const float* __restrict__ qkv_w,
                               const float* __restrict__ proj_w,
                               const float* __restrict__ fc1_w,
                               const float* __restrict__ fc2_w)
{
    int i = blockIdx.x * 256 + threadIdx.x;
    if (i >= NCVT) return;
    if (i < NQKV) {
        g_wqkv[i] = __float2bfloat16(qkv_w[i]);
    } else if (i < NQKV + NPROJ) {
        int j = i - NQKV;
        g_wproj[j] = __float2bfloat16(proj_w[j]);
    } else if (i < NQKV + NPROJ + NFC1) {
        int j = i - NQKV - NPROJ;
        g_wfc1[j] = __float2bfloat16(fc1_w[j]);
    } else {
        int j = i - NQKV - NPROJ - NFC1;
        g_wfc2[j] = __float2bfloat16(fc2_w[j]);
    }
}

// ---------------- fused bias table: rpb + shift-mask + padding ------------------
__global__ void bias_kernel(const float* __restrict__ rpb_t)
{
    int idx = blockIdx.x * 256 + threadIdx.x;
    if (idx >= NBIAS) return;
    int j   = idx & 63;
    int i   = (idx >> 6) & 63;
    int h   = (idx >> 12) % NHh;
    int pat = idx / (NHh * 4096);
    float v;
    if (i >= Nwin || j >= Nwin) {
        v = -1e9f;
    } else {
        int ri = i / WSz, ci = i % WSz;
        int rj = j / WSz, cj = j % WSz;
        int ph = pat >> 1, pw = pat & 1;
        int ghi = ph ? (ri < 4 ? 1 : 2) : 0;
        int gwi = pw ? (ci < 4 ? 1 : 2) : 0;
        int ghj = ph ? (rj < 4 ? 1 : 2) : 0;
        int gwj = pw ? (cj < 4 ? 1 : 2) : 0;
        int gi = ghi * 3 + gwi;
        int gj = ghj * 3 + gwj;
        v = rpb_t[((ri - rj + 6) * 13 + (ci - cj + 6)) * NHh + h]
          + (gi != gj ? -100.f : 0.f);
    }
    g_bias[idx] = __float2bfloat16(v);
}

// ---------------- LN1 + shift + window-partition -------------------------------
__global__ void __launch_bounds__(256) ln1_window_kernel(
    const float* __restrict__ x, const float* __restrict__ g,
    const float* __restrict__ b)
{
    int warp = (blockIdx.x * blockDim.x + threadIdx.x) >> 5;
    int lane = threadIdx.x & 31;
    if (warp >= TOK) return;
    int bidx = warp / Ltok;
    int l    = warp % Ltok;
    const float* xr = x + (size_t)warp * Cch;
    float v[6];
    float s = 0.f;
    float ss = 0.f;
#pragma unroll
    for (int i = 0; i < 6; i++) {
        v[i] = xr[lane + 32 * i];
        s  += v[i];
        ss += v[i] * v[i];
    }
#pragma unroll
    for (int o = 16; o; o >>= 1) {
        s  += __shfl_xor_sync(0xffffffffu, s,  o);
        ss += __shfl_xor_sync(0xffffffffu, ss, o);
    }
    float mean = s * (1.f / Cch);
    float rstd = rsqrtf(ss * (1.f / Cch) - mean * mean + 1e-5f);

    int h = l / Wdim;
    int w = l % Wdim;
    int hs = h - SSz; if (hs < 0) hs += Hdim;
    int ws = w - SSz; if (ws < 0) ws += Wdim;
    int wh = hs / WSz;
    int r  = hs % WSz;
    int ww = ws / WSz;
    int c  = ws % WSz;
    int row = (bidx * NWIN + wh * NWW + ww) * Nwin + r * WSz + c;
    bf16* dst = g_xw + (size_t)row * Cch;
#pragma unroll
    for (int i = 0; i < 6; i++) {
        int ch = lane + 32 * i;
        dst[ch] = __float2bfloat16((v[i] - mean) * rstd * g[ch] + b[ch]);
    }
}

// ---------------- LN2 -----------------------------------------------------------
__global__ void __launch_bounds__(256) ln2_kernel(
    const float* __restrict__ x, const float* __restrict__ g,
    const float* __restrict__ b)
{
    int warp = (blockIdx.x * blockDim.x + threadIdx.x) >> 5;
    int lane = threadIdx.x & 31;
    if (warp >= TOK) return;
    const float* xr = x + (size_t)warp * Cch;
    float v[6];
    float s = 0.f;
    float ss = 0.f;
#pragma unroll
    for (int i = 0; i < 6; i++) {
        v[i] = xr[lane + 32 * i];
        s  += v[i];
        ss += v[i] * v[i];
    }
#pragma unroll
    for (int o = 16; o; o >>= 1) {
        s  += __shfl_xor_sync(0xffffffffu, s,  o);
        ss += __shfl_xor_sync(0xffffffffu, ss, o);
    }
    float mean = s * (1.f / Cch);
    float rstd = rsqrtf(ss * (1.f / Cch) - mean * mean + 1e-5f);
    bf16* dst = g_xw + (size_t)warp * Cch;
#pragma unroll
    for (int i = 0; i < 6; i++) {
        int ch = lane + 32 * i;
        dst[ch] = __float2bfloat16((v[i] - mean) * rstd * g[ch] + b[ch]);
    }
}

// ---------------- mma / ldmatrix helpers -----------------------------------------
__device__ __forceinline__ void ldsm_x4(uint32_t& r0, uint32_t& r1, uint32_t& r2,
                                        uint32_t& r3, const void* p)
{
    uint32_t a = (uint32_t)__cvta_generic_to_shared(p);
    asm volatile("ldmatrix.sync.aligned.m8n8.x4.shared.b16 {%0,%1,%2,%3},[%4];"
                 : "=r"(r0), "=r"(r1), "=r"(r2), "=r"(r3) : "r"(a));
}
__device__ __forceinline__ void ldsm_x4_t(uint32_t& r0, uint32_t& r1, uint32_t& r2,
                                          uint32_t& r3, const void* p)
{
    uint32_t a = (uint32_t)__cvta_generic_to_shared(p);
    asm volatile("ldmatrix.sync.aligned.m8n8.x4.trans.shared.b16 {%0,%1,%2,%3},[%4];"
                 : "=r"(r0), "=r"(r1), "=r"(r2), "=r"(r3) : "r"(a));
}
__device__ __forceinline__ void mma_bf16(float* c, const uint32_t* a, const uint32_t* b)
{
    asm volatile(
        "mma.sync.aligned.m16n8k16.row.col.f32.bf16.bf16.f32 "
        "{%0,%1,%2,%3},{%4,%5,%6,%7},{%8,%9},{%0,%1,%2,%3};"
        : "+f"(c[0]), "+f"(c[1]), "+f"(c[2]), "+f"(c[3])
        : "r"(a[0]), "r"(a[1]), "r"(a[2]), "r"(a[3]), "r"(b[0]), "r"(b[1]));
}
__device__ __forceinline__ void cp16(void* smem, const void* gmem)
{
    uint32_t a = (uint32_t)__cvta_generic_to_shared(smem);
    asm volatile("cp.async.cg.shared.global [%0], [%1], 16;" :: "r"(a), "l"(gmem));
}
__device__ __forceinline__ void cp_commit()
{
    asm volatile("cp.async.commit_group;" ::: "memory");
}
__device__ __forceinline__ void cp_wait1()
{
    asm volatile("cp.async.wait_group 1;" ::: "memory");
}

// ---------------- bf16 tensor-core GEMM (BM=128, 3-stage cp.async ring) -----------
#define BM 128
#define BN 64
#define BK 32
#define ASTRIDE 40
#define BSTRIDE 72

// MODE 0: bf16 store scattered to head-major qkv layout (q pre-scaled)
// MODE 1: fp32 store, window-reverse + unshift + residual -> d_out
// MODE 2: exact GELU -> bf16 store (hidden)
// MODE 3: fp32 += (fc2 residual into d_out)
template <int MODE>
__device__ __forceinline__ void hgemm_body(
    const bf16* A, const bf16* Bw, const float* bias, void* Cout,
    int Kd, int Nd, const float* resid)
{
    __shared__ bf16 As[3][BM][ASTRIDE];
    __shared__ bf16 Bs[3][BK][BSTRIDE];

    int tid  = threadIdx.x;
    int warp = tid >> 5;
    int lane = tid & 31;
    int wm = warp >> 1;
    int wn = warp & 1;
    int row0 = blockIdx.y * BM;
    int col0 = blockIdx.x * BN;

    float acc[2][4][4];
#pragma unroll
    for (int i = 0; i < 2; i++)
#pragma unroll
        for (int j = 0; j < 4; j++)
#pragma unroll
            for (int k = 0; k < 4; k++) acc[i][j][k] = 0.f;

    int ra0 = tid >> 2;
    int ka0 = (tid & 3) * 8;
    int ra1 = ra0 + 64;
    int rb = tid >> 3;
    int kb = (tid & 7) * 8;

    const bf16* Ag0 = A + (size_t)(row0 + ra0) * Kd + ka0;
    const bf16* Ag1 = A + (size_t)(row0 + ra1) * Kd + ka0;
    const bf16* Bg  = Bw + (size_t)rb * Nd + col0 + kb;

    int nit = Kd / BK;

    cp16(&As[0][ra0][ka0], Ag0);
    cp16(&As[0][ra1][ka0], Ag1);
    cp16(&Bs[0][rb][kb],   Bg);
    cp_commit();
    if (nit > 1) {
        cp16(&As[1][ra0][ka0], Ag0 + BK);
        cp16(&As[1][ra1][ka0], Ag1 + BK);
        cp16(&Bs[1][rb][kb],   Bg + (size_t)BK * Nd);
    }
    cp_commit();

    int buf = 0;
    int ld  = 2;
    for (int it = 0; it < nit; it++) {
        cp_wait1();
        __syncthreads();
        if (it + 2 < nit) {
            int k2 = (it + 2) * BK;
            cp16(&As[ld][ra0][ka0], Ag0 + k2);
            cp16(&As[ld][ra1][ka0], Ag1 + k2);
            cp16(&Bs[ld][rb][kb],   Bg + (size_t)k2 * Nd);
            cp_commit();
            ld = (ld == 2) ? 0 : ld + 1;
        } else {
            cp_commit();
        }

#pragma unroll
        for (int ks = 0; ks < 2; ks++) {
            uint32_t af[2][4];
            uint32_t bfr[4][2];
#pragma unroll
            for (int mt = 0; mt < 2; mt++)
                ldsm_x4(af[mt][0], af[mt][1], af[mt][2], af[mt][3],
                        &As[buf][wm * 32 + mt * 16 + (lane & 15)][ks * 16 + (lane >> 4) * 8]);
#pragma unroll
            for (int bt = 0; bt < 2; bt++) {
                uint32_t r0, r1, r2, r3;
                ldsm_x4_t(r0, r1, r2, r3,
                          &Bs[buf][ks * 16 + (lane & 15)][wn * 32 + bt * 16 + (lane >> 4) * 8]);
                bfr[bt * 2][0] = r0;
                bfr[bt * 2][1] = r1;
                bfr[bt * 2 + 1][0] = r2;
                bfr[bt * 2 + 1][1] = r3;
            }
#pragma unroll
            for (int mt = 0; mt < 2; mt++)
#pragma unroll
                for (int nt = 0; nt < 4; nt++)
                    mma_bf16(acc[mt][nt], af[mt], bfr[nt]);
        }
        buf = (buf == 2) ? 0 : buf + 1;
    }

#pragma unroll
    for (int mt = 0; mt < 2; mt++) {
#pragma unroll
        for (int rh = 0; rh < 2; rh++) {
            int row = row0 + wm * 32 + mt * 16 + rh * 8 + (lane >> 2);
            size_t dstrow = 0;
            int winq = 0;
            int nq = 0;
            if (MODE == 1) {
                int win = row / Nwin;
                int n = row % Nwin;
                int bb = win / NWIN;
                int w_ = win % NWIN;
                int wh = w_ / NWW;
                int ww = w_ % NWW;
                int h = wh * WSz + n / WSz + SSz; if (h >= Hdim) h -= Hdim;
                int w = ww * WSz + n % WSz + SSz; if (w >= Wdim) w -= Wdim;
                dstrow = ((size_t)bb * Ltok + h * Wdim + w) * Cch;
            } else if (MODE == 0) {
                winq = row / Nwin;
                nq   = row % Nwin;
            } else {
                dstrow = (size_t)row * Nd;
            }
#pragma unroll
            for (int nt = 0; nt < 4; nt++) {
                int col = col0 + wn * 32 + nt * 8 + (lane & 3) * 2;
                float v0 = acc[mt][nt][rh * 2 + 0] + bias[col];
                float v1 = acc[mt][nt][rh * 2 + 1] + bias[col + 1];
                if (MODE == 0) {
                    int sel = col / Cch;
                    int hd2 = (col % Cch) >> 5;
                    int d   = col & 31;
                    if (sel == 0) {
                        v0 *= 0.1767766952966369f;
                        v1 *= 0.1767766952966369f;
                    }
                    size_t off = (((size_t)winq * 3 + sel) * NHh + hd2) * WINTILE
                               + nq * HD + d;
                    *(__nv_bfloat162*)((bf16*)Cout + off) =
                        __halves2bfloat162(__float2bfloat16(v0), __float2bfloat16(v1));
                } else if (MODE == 2) {
                    float g0 = 0.5f * v0 * (1.f + erff(v0 * 0.7071067811865475f));
                    float g1 = 0.5f * v1 * (1.f + erff(v1 * 0.7071067811865475f));
                    *(__nv_bfloat162*)((bf16*)Cout + dstrow + col) =
                        __halves2bfloat162(__float2bfloat16(g0), __float2bfloat16(g1));
                } else if (MODE == 1) {
                    float* o = (float*)Cout + dstrow + col;
                    o[0] = resid[dstrow + col]     + v0;
                    o[1] = resid[dstrow + col + 1] + v1;
                } else {
                    float* o = (float*)Cout + dstrow + col;
                    o[0] += v0;
                    o[1] += v1;
                }
            }
        }
    }
}

// ---------------- concrete GEMM wrappers (force 4 CTAs/SM) -------------------------
__global__ void __launch_bounds__(256, 4) hgemm_qkv(const float* __restrict__ bias)
{
    hgemm_body<0>(g_xw, g_wqkv, bias, g_qkv, Cch, CQKV, (const float*)0);
}
__global__ void __launch_bounds__(256, 4) hgemm_proj(const float* __restrict__ bias,
                                                     float* __restrict__ out,
                                                     const float* __restrict__ resid)
{
    hgemm_body<1>(g_att, g_wproj, bias, out, Cch, Cch, resid);
}
__global__ void __launch_bounds__(256, 4) hgemm_fc1(const float* __restrict__ bias)
{
    hgemm_body<2>(g_xw, g_wfc1, bias, g_hid, Cch, HID, (const float*)0);
}
__global__ void __launch_bounds__(256, 4) hgemm_fc2(const float* __restrict__ bias,
                                                    float* __restrict__ out)
{
    hgemm_body<3>(g_hid, g_wfc2, bias, out, HID, Cch, (const float*)0);
}

// ---------------- windowed attention: 2 heads/block, fused bias table --------------
__global__ void __launch_bounds__(256) attn_kernel()
{
    __shared__ bf16  qk[2][2][64][40];
    __shared__ bf16  vs[2][64][40];

    int tid  = threadIdx.x;
    int warp = tid >> 5;
    int lane = tid & 31;
    int hh   = warp >> 2;
    int wg   = warp & 3;
    int m0   = wg * 16;

    int blk  = blockIdx.x;
    int hb   = blk % 3;
    int win  = blk / 3;
    int wwin = win % NWIN;
    int pat  = ((wwin / NWW == NWH - 1) ? 2 : 0) + ((wwin % NWW == NWW - 1) ? 1 : 0);

    {
        int t   = tid & 127;
        int lh  = tid >> 7;
        int head = 2 * hb + lh;
        const bf16* bq = g_qkv + (((size_t)win * 3 + 0) * NHh + head) * WINTILE;
        const bf16* bk = g_qkv + (((size_t)win * 3 + 1) * NHh + head) * WINTILE;
        const bf16* bv = g_qkv + (((size_t)win * 3 + 2) * NHh + head) * WINTILE;
        for (int idx = t; idx < 196; idx += 128) {
            int row = idx >> 2;
            int c   = (idx & 3) * 8;
            *(uint4*)&qk[lh][0][row][c] = *(const uint4*)(bq + idx * 8);
            *(uint4*)&qk[lh][1][row][c] = *(const uint4*)(bk + idx * 8);
            *(uint4*)&vs[lh][row][c]    = *(const uint4*)(bv + idx * 8);
        }
        for (int idx = t; idx < 150; idx += 128) {
            int r  = 49 + idx / 10;
            int c4 = (idx % 10) * 4;
            uint2 z = make_uint2(0u, 0u);
            *(uint2*)&qk[lh][0][r][c4] = z;
            *(uint2*)&qk[lh][1][r][c4] = z;
            *(uint2*)&vs[lh][r][c4]    = z;
        }
    }
    __syncthreads();

    float c[8][4];
#pragma unroll
    for (int nt = 0; nt < 8; nt++)
#pragma unroll
        for (int e = 0; e < 4; e++) c[nt][e] = 0.f;
    {
        uint32_t a[2][4];
#pragma unroll
        for (int ksx = 0; ksx < 2; ksx++)
            ldsm_x4(a[ksx][0], a[ksx][1], a[ksx][2], a[ksx][3],
                    &qk[hh][0][m0 + (lane & 15)][ksx * 16 + (lane >> 4) * 8]);
#pragma unroll
        for (int jt = 0; jt < 4; jt++) {
#pragma unroll
            for (int ksx = 0; ksx < 2; ksx++) {
                uint32_t r0, r1, r2, r3;
                ldsm_x4(r0, r1, r2, r3,
                        &qk[hh][1][jt * 16 + (lane & 15)][ksx * 16 + (lane >> 4) * 8]);
                uint32_t b0[2];
                uint32_t b1[2];
                b0[0] = r0; b0[1] = r2;
                b1[0] = r1; b1[1] = r3;
                mma_bf16(c[jt * 2],     a[ksx], b0);
                mma_bf16(c[jt * 2 + 1], a[ksx], b1);
            }
        }
    }
    __syncthreads();

    bf16* psp = &qk[hh][0][0][0];

    {
        int head = 2 * hb + hh;
        int i0 = m0 + (lane >> 2);
        int i1 = i0 + 8;
        int j0 = (lane & 3) * 2;
        const bf16* brow = g_bias + ((size_t)pat * NHh + head) * 4096;

#pragma unroll
        for (int nt = 0; nt < 8; nt++) {
            __nv_bfloat162 b0 = *(const __nv_bfloat162*)(brow + i0 * 64 + nt * 8 + j0);
            __nv_bfloat162 b1 = *(const __nv_bfloat162*)(brow + i1 * 64 + nt * 8 + j0);
            float2 f0 = __bfloat1622float2(b0);
            float2 f1 = __bfloat1622float2(b1);
            c[nt][0] += f0.x;
            c[nt][1] += f0.y;
            c[nt][2] += f1.x;
            c[nt][3] += f1.y;
        }

        float mx0 = -1e30f;
        float mx1 = -1e30f;
#pragma unroll
        for (int nt = 0; nt < 8; nt++) {
            mx0 = fmaxf(mx0, fmaxf(c[nt][0], c[nt][1]));
            mx1 = fmaxf(mx1, fmaxf(c[nt][2], c[nt][3]));
        }
        mx0 = fmaxf(mx0, __shfl_xor_sync(0xffffffffu, mx0, 1));
        mx0 = fmaxf(mx0, __shfl_xor_sync(0xffffffffu, mx0, 2));
        mx1 = fmaxf(mx1, __shfl_xor_sync(0xffffffffu, mx1, 1));
        mx1 = fmaxf(mx1, __shfl_xor_sync(0xffffffffu, mx1, 2));

        float sm0 = 0.f;
        float sm1 = 0.f;
#pragma unroll
        for (int nt = 0; nt < 8; nt++) {
            c[nt][0] = __expf(c[nt][0] - mx0);
            c[nt][1] = __expf(c[nt][1] - mx0);
            c[nt][2] = __expf(c[nt][2] - mx1);
            c[nt][3] = __expf(c[nt][3] - mx1);
            sm0 += c[nt][0] + c[nt][1];
            sm1 += c[nt][2] + c[nt][3];
        }
        sm0 += __shfl_xor_sync(0xffffffffu, sm0, 1);
        sm0 += __shfl_xor_sync(0xffffffffu, sm0, 2);
        sm1 += __shfl_xor_sync(0xffffffffu, sm1, 1);
        sm1 += __shfl_xor_sync(0xffffffffu, sm1, 2);
        float inv0 = 1.f / sm0;
        float inv1 = 1.f / sm1;

#pragma unroll
        for (int nt = 0; nt < 8; nt++) {
            *(__nv_bfloat162*)&psp[i0 * 72 + nt * 8 + j0] =
                __halves2bfloat162(__float2bfloat16(c[nt][0] * inv0),
                                   __float2bfloat16(c[nt][1] * inv0));
            *(__nv_bfloat162*)&psp[i1 * 72 + nt * 8 + j0] =
                __halves2bfloat162(__float2bfloat16(c[nt][2] * inv1),
                                   __float2bfloat16(c[nt][3] * inv1));
        }
    }
    __syncthreads();

    {
        float o[4][4];
#pragma unroll
        for (int nt = 0; nt < 4; nt++)
#pragma unroll
            for (int e = 0; e < 4; e++) o[nt][e] = 0.f;

#pragma unroll
        for (int ksx = 0; ksx < 4; ksx++) {
            uint32_t a[4];
            ldsm_x4(a[0], a[1], a[2], a[3],
                    &psp[(m0 + (lane & 15)) * 72 + ksx * 16 + (lane >> 4) * 8]);
#pragma unroll
            for (int bt = 0; bt < 2; bt++) {
                uint32_t r0, r1, r2, r3;
                ldsm_x4_t(r0, r1, r2, r3,
                          &vs[hh][ksx * 16 + (lane & 15)][bt * 16 + (lane >> 4) * 8]);
                uint32_t b0[2];
                uint32_t b1[2];
                b0[0] = r0; b0[1] = r1;
                b1[0] = r2; b1[1] = r3;
                mma_bf16(o[bt * 2],     a, b0);
                mma_bf16(o[bt * 2 + 1], a, b1);
            }
        }

        bf16* outw = g_att + (size_t)win * Nwin * Cch + (2 * hb + hh) * HD;
        int i0 = m0 + (lane >> 2);
#pragma unroll
        for (int nt = 0; nt < 4; nt++) {
            int d = nt * 8 + (lane & 3) * 2;
            if (i0 < Nwin) {
                *(__nv_bfloat162*)(outw + (size_t)i0 * Cch + d) =
                    __halves2bfloat162(__float2bfloat16(o[nt][0]), __float2bfloat16(o[nt][1]));
            }
            if (i0 + 8 < Nwin) {
                *(__nv_bfloat162*)(outw + (size_t)(i0 + 8) * Cch + d) =
                    __halves2bfloat162(__float2bfloat16(o[nt][2]), __float2bfloat16(o[nt][3]));
            }
        }
    }
}

// ---------------- launch ----------------------------------------------------------
extern "C" void kernel_launch(void* const* d_in, const int* in_sizes, int n_in,
                              void* d_out, int out_size)
{
    const float* x       = (const float*)d_in[0];
    const float* norm1_g = (const float*)d_in[1];
    const float* norm1_b = (const float*)d_in[2];
    const float* qkv_w   = (const float*)d_in[3];
    const float* qkv_b   = (const float*)d_in[4];
    const float* rpb_t   = (const float*)d_in[5];
    const float* proj_w  = (const float*)d_in[6];
    const float* proj_b  = (const float*)d_in[7];
    const float* norm2_g = (const float*)d_in[8];
    const float* norm2_b = (const float*)d_in[9];
    const float* fc1_w   = (const float*)d_in[10];
    const float* fc1_b   = (const float*)d_in[11];
    const float* fc2_w   = (const float*)d_in[12];
    const float* fc2_b   = (const float*)d_in[13];
    float* out = (float*)d_out;

    dim3 cvt_grid((NCVT + 255) / 256);
    cvt_all_kernel<<<cvt_grid, 256>>>(qkv_w, proj_w, fc1_w, fc2_w);

    dim3 bias_grid((NBIAS + 255) / 256);
    bias_kernel<<<bias_grid, 256>>>(rpb_t);

    dim3 ln_grid(TOK / 8);
    ln1_window_kernel<<<ln_grid, 256>>>(x, norm1_g, norm1_b);

    dim3 qkv_grid(CQKV / BN, TOK / BM);
    hgemm_qkv<<<qkv_grid, 256>>>(qkv_b);

    dim3 attn_grid((TOK / Nwin) * 3);
    attn_kernel<<<attn_grid, 256>>>();

    dim3 proj_grid(Cch / BN, TOK / BM);
    hgemm_proj<<<proj_grid, 256>>>(proj_b, out, x);

    ln2_kernel<<<ln_grid, 256>>>(out, norm2_g, norm2_b);

    dim3 fc1_grid(HID / BN, TOK / BM);
    hgemm_fc1<<<fc1_grid, 256>>>(fc1_b);

    dim3 fc2_grid(Cch / BN, TOK / BM);
    hgemm_fc2<<<fc2_grid, 256>>>(fc2_b, out);
}